// round 11
// baseline (speedup 1.0000x reference)
#include <cuda_runtime.h>
#include <cuda_fp16.h>
#include <math.h>
#include <stdint.h>

#define BB 4
#define TT 2048
#define CC 1024
#define HH 16
#define DHH 64
#define DFF 4096
#define MM (BB*TT)   /* 8192 */

// -------- scratch (device globals; no allocation) --------
__device__ __half g_xnh[(size_t)MM*CC];
__device__ __half g_xnl[(size_t)MM*CC];
__device__ __half g_qhh[(size_t)MM*CC];
__device__ __half g_qll[(size_t)MM*CC];
__device__ __half g_khh[(size_t)MM*CC];
__device__ __half g_kll[(size_t)MM*CC];
__device__ __half g_vhh[(size_t)MM*CC];
__device__ __half g_ohh[(size_t)MM*CC];
__device__ __half g_x2h[(size_t)MM*CC];
__device__ __half g_ffh[(size_t)MM*DFF];
__device__ float  g_x1 [(size_t)MM*CC];
__device__ __half g_wqh[(size_t)CC*3072];
__device__ __half g_wql[(size_t)CC*3072];
__device__ __half g_wot[(size_t)CC*CC];
__device__ __half g_w1t[(size_t)CC*DFF];
__device__ __half g_w2t[(size_t)DFF*CC];

// ======================= helpers =======================
__device__ __forceinline__ uint32_t smem_u32(const void* p) {
    return (uint32_t)__cvta_generic_to_shared(p);
}
__device__ __forceinline__ float ex2f(float x) {
    float r;
    asm("ex2.approx.f32 %0, %1;" : "=f"(r) : "f"(x));
    return r;
}
#define LDM_X4(r0,r1,r2,r3, addr) \
    asm volatile("ldmatrix.sync.aligned.m8n8.x4.shared.b16 {%0,%1,%2,%3},[%4];" \
        : "=r"(r0),"=r"(r1),"=r"(r2),"=r"(r3) : "r"(addr))
#define LDM_X4T(r0,r1,r2,r3, addr) \
    asm volatile("ldmatrix.sync.aligned.m8n8.x4.trans.shared.b16 {%0,%1,%2,%3},[%4];" \
        : "=r"(r0),"=r"(r1),"=r"(r2),"=r"(r3) : "r"(addr))
#define MMA_F16(d, a0,a1,a2,a3, b0,b1) \
    asm volatile("mma.sync.aligned.m16n8k16.row.col.f32.f16.f16.f32 " \
        "{%0,%1,%2,%3},{%4,%5,%6,%7},{%8,%9},{%0,%1,%2,%3};" \
        : "+f"(d[0]),"+f"(d[1]),"+f"(d[2]),"+f"(d[3]) \
        : "r"(a0),"r"(a1),"r"(a2),"r"(a3),"r"(b0),"r"(b1))

__device__ __forceinline__ void cpa16(uint32_t dst, const void* src) {
    asm volatile("cp.async.cg.shared.global [%0], [%1], 16;\n" :: "r"(dst), "l"(src));
}
__device__ __forceinline__ void cpcommit() { asm volatile("cp.async.commit_group;\n" ::); }
template<int N> __device__ __forceinline__ void cpwait() {
    asm volatile("cp.async.wait_group %0;\n" :: "n"(N));
}

// ======================= prep kernels =======================
// Wqkv [H][C][DH] -> Th/Tl [n=3072][k=1024], vectorized 64x64 transpose
__global__ void prep_qkv_h(const float* __restrict__ Wq, const float* __restrict__ Wk,
                           const float* __restrict__ Wv,
                           __half* __restrict__ Th, __half* __restrict__ Tl) {
    __shared__ float t[64][65];
    int k0 = blockIdx.x * 64;
    int nt = blockIdx.y;                 // 0..47
    int mat = nt >> 4, h = nt & 15;
    const float* W = (mat == 0) ? Wq : (mat == 1) ? Wk : Wv;
    int tid = threadIdx.x;
    int ty = tid >> 4, tx = tid & 15;    // load: 16 rows/pass, 16 f4 groups
    #pragma unroll
    for (int j = 0; j < 4; j++) {
        int ky = ty + 16 * j;
        float4 v = *(const float4*)(W + h * 65536 + (size_t)(k0 + ky) * 64 + tx * 4);
        t[ky][tx*4+0] = v.x; t[ky][tx*4+1] = v.y;
        t[ky][tx*4+2] = v.z; t[ky][tx*4+3] = v.w;
    }
    __syncthreads();
    int nr = tid >> 2, kc = (tid & 3) * 16;   // out: d-row nr, k chunk kc
    __half hh[16], hl[16];
    #pragma unroll
    for (int i = 0; i < 16; i++) {
        float w = t[kc + i][nr];
        __half hi = __float2half_rn(w);
        hh[i] = hi;
        hl[i] = __float2half_rn(w - __half2float(hi));
    }
    size_t n = (size_t)(mat * 1024 + h * 64 + nr);
    uint4* dh = (uint4*)(Th + n * CC + k0 + kc);
    uint4* dl = (uint4*)(Tl + n * CC + k0 + kc);
    dh[0] = *(uint4*)&hh[0]; dh[1] = *(uint4*)&hh[8];
    dl[0] = *(uint4*)&hl[0]; dl[1] = *(uint4*)&hl[8];
}

// W[K][N] f32 -> Wt[N][K] fp16, 64x64 tiles (validated R9: 2.1 TB/s)
__global__ void prep_t(const float* __restrict__ W, __half* __restrict__ Wt, int K, int N) {
    __shared__ float t[64][65];
    int n0 = blockIdx.x * 64, k0 = blockIdx.y * 64;
    int tid = threadIdx.x;
    int ty = tid >> 4, tx = tid & 15;
    #pragma unroll
    for (int j = 0; j < 4; j++) {
        float4 v = *(const float4*)(W + (size_t)(k0 + ty + 16*j) * N + n0 + tx*4);
        t[ty + 16*j][tx*4+0] = v.x; t[ty + 16*j][tx*4+1] = v.y;
        t[ty + 16*j][tx*4+2] = v.z; t[ty + 16*j][tx*4+3] = v.w;
    }
    __syncthreads();
    int nr = tid >> 2, kc = (tid & 3) * 16;
    __half h16[16];
    #pragma unroll
    for (int i = 0; i < 16; i++) h16[i] = __float2half_rn(t[kc + i][nr]);
    uint4* dst = (uint4*)(Wt + (size_t)(n0 + nr) * K + k0 + kc);
    dst[0] = *(uint4*)&h16[0];
    dst[1] = *(uint4*)&h16[8];
}

// ======================= LayerNorm (f32 in, fp16 out) =======================
template<int MODE>   // 2 = hi+lo, 1 = hi only
__global__ void ln_h(const float* __restrict__ X, const float* __restrict__ gam,
                     const float* __restrict__ bet,
                     __half* __restrict__ Yh, __half* __restrict__ Yl) {
    int row = blockIdx.x;
    const float* xr = X + (size_t)row * CC;
    int tid = threadIdx.x;
    float4 v = *(const float4*)(xr + tid * 4);
    float s  = v.x + v.y + v.z + v.w;
    float ss = v.x*v.x + v.y*v.y + v.z*v.z + v.w*v.w;
    #pragma unroll
    for (int off = 16; off >= 1; off >>= 1) {
        s  += __shfl_xor_sync(0xffffffffu, s,  off);
        ss += __shfl_xor_sync(0xffffffffu, ss, off);
    }
    __shared__ float sb[8], ssb[8];
    if ((tid & 31) == 0) { sb[tid >> 5] = s; ssb[tid >> 5] = ss; }
    __syncthreads();
    s = 0.f; ss = 0.f;
    #pragma unroll
    for (int w = 0; w < 8; w++) { s += sb[w]; ss += ssb[w]; }
    float mu  = s * (1.0f / CC);
    float var = ss * (1.0f / CC) - mu * mu;
    float rs  = rsqrtf(var + 1e-5f);
    float4 gv = *(const float4*)(gam + tid * 4);
    float4 bv = *(const float4*)(bet + tid * 4);
    float y[4];
    y[0] = (v.x - mu) * rs * gv.x + bv.x;
    y[1] = (v.y - mu) * rs * gv.y + bv.y;
    y[2] = (v.z - mu) * rs * gv.z + bv.z;
    y[3] = (v.w - mu) * rs * gv.w + bv.w;
    __half h[4];
    #pragma unroll
    for (int i = 0; i < 4; i++) h[i] = __float2half_rn(y[i]);
    int off = row * CC + tid * 4;
    half2 a = __halves2half2(h[0], h[1]);
    half2 b = __halves2half2(h[2], h[3]);
    uint2 u; u.x = *(uint32_t*)&a; u.y = *(uint32_t*)&b;
    *(uint2*)(Yh + off) = u;
    if (MODE == 2) {
        __half lo[4];
        #pragma unroll
        for (int i = 0; i < 4; i++) lo[i] = __float2half_rn(y[i] - __half2float(h[i]));
        half2 c = __halves2half2(lo[0], lo[1]);
        half2 d = __halves2half2(lo[2], lo[3]);
        uint2 w; w.x = *(uint32_t*)&c; w.y = *(uint32_t*)&d;
        *(uint2*)(Yl + off) = w;
    }
}

// ============ fp16 GEMM: 128x128x32 tiles, 5-stage pipeline, occ 2 ============
#define GP 40                 // smem pitch in halves
#define GST 5120              // stage stride in halves (128*40)
#define NSTG 5
#define G_SMEM (NSTG*GST*2*2) // 102400 bytes
template<bool RELU, bool RESID, bool OUTH>
__global__ __launch_bounds__(256, 2) void gemm_h(
        const __half* __restrict__ A, const __half* __restrict__ Bt,
        const float* __restrict__ bias, const float* __restrict__ resid,
        void* __restrict__ Cv, int M, int N, int K) {
    extern __shared__ __half gsm[];
    __half* As = gsm;                 // [NSTG][GST]
    __half* Bs = gsm + NSTG*GST;
    int tid = threadIdx.x, l = tid & 31, warp = tid >> 5;
    int wy = warp >> 2, wx = warp & 3, lr = l >> 2, lc = l & 3;
    int m0 = blockIdx.y * 128, n0 = blockIdx.x * 128;
    int a_row = (l & 7) + ((l >> 3) & 1) * 8, a_k = (l >> 4) * 8;
    int b_row = (l & 7) + ((l >> 4) & 1) * 8, b_k = ((l >> 3) & 1) * 8;
    float acc[4][4][4];
    #pragma unroll
    for (int i = 0; i < 4; i++)
        #pragma unroll
        for (int j = 0; j < 4; j++)
            #pragma unroll
            for (int f = 0; f < 4; f++) acc[i][j][f] = 0.f;
    uint32_t sA = smem_u32(As), sB = smem_u32(Bs);
    int r1c = tid >> 2, g1c = tid & 3;
    int r2c = (tid + 256) >> 2;
    const int NT = K >> 5;
    auto loadT = [&](int kt, int st) {
        int k0 = kt * 32;
        uint32_t o1 = (uint32_t)((st*GST + r1c*GP + g1c*8) * 2);
        uint32_t o2 = (uint32_t)((st*GST + r2c*GP + g1c*8) * 2);
        cpa16(sA + o1, A + (size_t)(m0 + r1c) * K + k0 + g1c*8);
        cpa16(sA + o2, A + (size_t)(m0 + r2c) * K + k0 + g1c*8);
        cpa16(sB + o1, Bt + (size_t)(n0 + r1c) * K + k0 + g1c*8);
        cpa16(sB + o2, Bt + (size_t)(n0 + r2c) * K + k0 + g1c*8);
        cpcommit();
    };
    loadT(0, 0);
    loadT(1, 1);
    loadT(2, 2);
    loadT(3, 3);
    int st = 0, ldst = 4;
    for (int kt = 0; kt < NT; kt++) {
        cpwait<NSTG-2>();
        __syncthreads();
        if (kt + 4 < NT) {
            loadT(kt + 4, ldst);
            if (++ldst == NSTG) ldst = 0;
        }
        #pragma unroll
        for (int ks = 0; ks < 2; ks++) {
            uint32_t af[4][4], bf[4][2];
            #pragma unroll
            for (int mi = 0; mi < 4; mi++) {
                uint32_t ad = sA + (uint32_t)((st*GST + (wy*64 + mi*16 + a_row)*GP
                                               + ks*16 + a_k) * 2);
                LDM_X4(af[mi][0], af[mi][1], af[mi][2], af[mi][3], ad);
            }
            #pragma unroll
            for (int nb = 0; nb < 2; nb++) {
                uint32_t ad = sB + (uint32_t)((st*GST + (wx*32 + nb*16 + b_row)*GP
                                               + ks*16 + b_k) * 2);
                uint32_t q0,q1,q2,q3;
                LDM_X4(q0,q1,q2,q3, ad);
                bf[nb*2][0]=q0; bf[nb*2][1]=q1; bf[nb*2+1][0]=q2; bf[nb*2+1][1]=q3;
            }
            #pragma unroll
            for (int mi = 0; mi < 4; mi++)
                #pragma unroll
                for (int nj = 0; nj < 4; nj++)
                    MMA_F16(acc[mi][nj], af[mi][0],af[mi][1],af[mi][2],af[mi][3],
                            bf[nj][0], bf[nj][1]);
        }
        if (++st == NSTG) st = 0;
    }
    #pragma unroll
    for (int mi = 0; mi < 4; mi++) {
        #pragma unroll
        for (int nj = 0; nj < 4; nj++) {
            int row = m0 + wy*64 + mi*16 + lr;
            int col = n0 + wx*32 + nj*8 + 2*lc;
            float b0 = bias[col], b1 = bias[col+1];
            float v0 = acc[mi][nj][0] + b0, v1 = acc[mi][nj][1] + b1;
            float v2 = acc[mi][nj][2] + b0, v3 = acc[mi][nj][3] + b1;
            if (RESID) {
                float2 q0 = *(const float2*)(resid + (size_t)row * N + col);
                float2 q1 = *(const float2*)(resid + (size_t)(row+8) * N + col);
                v0 += q0.x; v1 += q0.y; v2 += q1.x; v3 += q1.y;
            }
            if (RELU) {
                v0 = fmaxf(v0, 0.f); v1 = fmaxf(v1, 0.f);
                v2 = fmaxf(v2, 0.f); v3 = fmaxf(v3, 0.f);
            }
            if (OUTH) {
                __half* C = (__half*)Cv;
                *(half2*)(C + (size_t)row * N + col)     = __floats2half2_rn(v0, v1);
                *(half2*)(C + (size_t)(row+8) * N + col) = __floats2half2_rn(v2, v3);
            } else {
                float* C = (float*)Cv;
                *(float2*)(C + (size_t)row * N + col)     = make_float2(v0, v1);
                *(float2*)(C + (size_t)(row+8) * N + col) = make_float2(v2, v3);
            }
        }
    }
}

// ============ QKV GEMM: 3-term fp16 split, S=3 pipeline ============
#define QST 5120
#define QNS 3
#define QKV_SMEM (QNS*QST*4*2)   // 122880 B
__global__ __launch_bounds__(256) void gemm_qkv_h(
        const __half* __restrict__ Ah_, const __half* __restrict__ Al_,
        const __half* __restrict__ Bh_, const __half* __restrict__ Bl_,
        const float* __restrict__ bq, const float* __restrict__ bk_,
        const float* __restrict__ bv_,
        __half* __restrict__ qh, __half* __restrict__ ql,
        __half* __restrict__ kh, __half* __restrict__ kl,
        __half* __restrict__ vh) {
    extern __shared__ __half smq[];
    __half* Ah = smq;                    // [QNS][5120]
    __half* Al = smq + QNS*QST;
    __half* Bh = smq + 2*QNS*QST;
    __half* Bl = smq + 3*QNS*QST;
    const int K = CC;
    int tid = threadIdx.x, l = tid & 31, warp = tid >> 5;
    int wy = warp >> 2, wx = warp & 3, lr = l >> 2, lc = l & 3;
    int m0 = blockIdx.y * 128, n0 = blockIdx.x * 128;
    int a_row = (l & 7) + ((l >> 3) & 1) * 8, a_k = (l >> 4) * 8;
    int b_row = (l & 7) + ((l >> 4) & 1) * 8, b_k = ((l >> 3) & 1) * 8;
    float acc[4][4][4];
    #pragma unroll
    for (int i = 0; i < 4; i++)
        #pragma unroll
        for (int j = 0; j < 4; j++)
            #pragma unroll
            for (int f = 0; f < 4; f++) acc[i][j][f] = 0.f;
    uint32_t sAh = smem_u32(Ah), sAl = smem_u32(Al);
    uint32_t sBh = smem_u32(Bh), sBl = smem_u32(Bl);
    int r1c = tid >> 2, g1c = tid & 3;
    int r2c = (tid + 256) >> 2;
    const int NT = K >> 5;
    auto pf = [&](int kt, int st) {
        int k0 = kt * 32;
        uint32_t o1 = (uint32_t)((st*QST + r1c*GP + g1c*8) * 2);
        uint32_t o2 = (uint32_t)((st*QST + r2c*GP + g1c*8) * 2);
        cpa16(sAh + o1, Ah_ + (size_t)(m0 + r1c) * K + k0 + g1c*8);
        cpa16(sAh + o2, Ah_ + (size_t)(m0 + r2c) * K + k0 + g1c*8);
        cpa16(sBh + o1, Bh_ + (size_t)(n0 + r1c) * K + k0 + g1c*8);
        cpa16(sBh + o2, Bh_ + (size_t)(n0 + r2c) * K + k0 + g1c*8);
        cpa16(sAl + o1, Al_ + (size_t)(m0 + r1c) * K + k0 + g1c*8);
        cpa16(sAl + o2, Al_ + (size_t)(m0 + r2c) * K + k0 + g1c*8);
        cpa16(sBl + o1, Bl_ + (size_t)(n0 + r1c) * K + k0 + g1c*8);
        cpa16(sBl + o2, Bl_ + (size_t)(n0 + r2c) * K + k0 + g1c*8);
        cpcommit();
    };
    pf(0, 0);
    pf(1, 1);
    int st = 0, ldst = 2;
    for (int kt = 0; kt < NT; kt++) {
        cpwait<1>();
        __syncthreads();
        if (kt + 2 < NT) {
            pf(kt + 2, ldst);
            if (++ldst == QNS) ldst = 0;
        }
        #pragma unroll
        for (int ks = 0; ks < 2; ks++) {
            uint32_t afh[4][4], afl[4][4];
            #pragma unroll
            for (int mi = 0; mi < 4; mi++) {
                uint32_t ao = (uint32_t)((st*QST + (wy*64 + mi*16 + a_row)*GP
                                          + ks*16 + a_k) * 2);
                LDM_X4(afh[mi][0], afh[mi][1], afh[mi][2], afh[mi][3], sAh + ao);
                LDM_X4(afl[mi][0], afl[mi][1], afl[mi][2], afl[mi][3], sAl + ao);
            }
            #pragma unroll
            for (int nb = 0; nb < 2; nb++) {
                uint32_t bo = (uint32_t)((st*QST + (wx*32 + nb*16 + b_row)*GP
                                          + ks*16 + b_k) * 2);
                uint32_t h0,h1,h2,h3, e0,e1,e2,e3;
                LDM_X4(h0,h1,h2,h3, sBh + bo);
                LDM_X4(e0,e1,e2,e3, sBl + bo);
                #pragma unroll
                for (int mi = 0; mi < 4; mi++) {
                    int nj = nb * 2;
                    MMA_F16(acc[mi][nj], afh[mi][0],afh[mi][1],afh[mi][2],afh[mi][3], e0,e1);
                    MMA_F16(acc[mi][nj], afl[mi][0],afl[mi][1],afl[mi][2],afl[mi][3], h0,h1);
                    MMA_F16(acc[mi][nj], afh[mi][0],afh[mi][1],afh[mi][2],afh[mi][3], h0,h1);
                    MMA_F16(acc[mi][nj+1], afh[mi][0],afh[mi][1],afh[mi][2],afh[mi][3], e2,e3);
                    MMA_F16(acc[mi][nj+1], afl[mi][0],afl[mi][1],afl[mi][2],afl[mi][3], h2,h3);
                    MMA_F16(acc[mi][nj+1], afh[mi][0],afh[mi][1],afh[mi][2],afh[mi][3], h2,h3);
                }
            }
        }
        if (++st == QNS) st = 0;
    }
    int mat = n0 >> 10, rem0 = n0 & 1023;
    const float* bias = (mat == 0) ? bq : (mat == 1) ? bk_ : bv_;
    // Q scaled by 8*log2(e): softmax runs in log2 domain
    float sc = (mat == 0) ? 8.0f * 1.4426950408889634f : 1.f;
    #pragma unroll
    for (int mi = 0; mi < 4; mi++) {
        #pragma unroll
        for (int nj = 0; nj < 4; nj++) {
            int row = m0 + wy*64 + mi*16 + lr;
            int col = rem0 + wx*32 + nj*8 + 2*lc;
            float b0 = bias[col], b1 = bias[col+1];
            float v0 = (acc[mi][nj][0] + b0) * sc, v1 = (acc[mi][nj][1] + b1) * sc;
            float v2 = (acc[mi][nj][2] + b0) * sc, v3 = (acc[mi][nj][3] + b1) * sc;
            size_t i0 = (size_t)row * CC + col, i1 = (size_t)(row+8) * CC + col;
            if (mat == 2) {
                *(half2*)(vh + i0) = __floats2half2_rn(v0, v1);
                *(half2*)(vh + i1) = __floats2half2_rn(v2, v3);
            } else {
                __half* oh = (mat == 0) ? qh : kh;
                __half* ol = (mat == 0) ? ql : kl;
                __half h0 = __float2half_rn(v0), h1 = __float2half_rn(v1);
                __half h2 = __float2half_rn(v2), h3 = __float2half_rn(v3);
                *(half2*)(oh + i0) = __halves2half2(h0, h1);
                *(half2*)(oh + i1) = __halves2half2(h2, h3);
                *(half2*)(ol + i0) = __halves2half2(
                    __float2half_rn(v0 - __half2float(h0)),
                    __float2half_rn(v1 - __half2float(h1)));
                *(half2*)(ol + i1) = __halves2half2(
                    __float2half_rn(v2 - __half2float(h2)),
                    __float2half_rn(v3 - __half2float(h3)));
            }
        }
    }
}

// ================= fp16 flash attention, BC=128, log2-domain softmax =================
#define PP 136
#define KSTG 9216
#define ATSMH (72704*2)
__global__ __launch_bounds__(256, 1) void attn_h(
        const __half* __restrict__ Qh_, const __half* __restrict__ Ql_,
        const __half* __restrict__ Kh_, const __half* __restrict__ Kl_,
        const __half* __restrict__ V_, __half* __restrict__ O_) {
    extern __shared__ __half sma[];
    __half* Ph = sma;
    __half* Kh = sma + 17408;
    __half* Kl = sma + 35840;
    __half* Vs = sma + 54272;
    uint32_t sPh = smem_u32(Ph), sKh = smem_u32(Kh), sKl = smem_u32(Kl), sVs = smem_u32(Vs);
    int tid = threadIdx.x, lane = tid & 31, warp = tid >> 5;
    int lr = lane >> 2, lc = lane & 3;
    int r0 = blockIdx.x * 128;
    int h  = blockIdx.y;
    int b  = blockIdx.z;
    size_t base = (size_t)b * TT * CC + h * DHH;

    int a_row = (lane & 7) + ((lane >> 3) & 1) * 8, a_k = (lane >> 4) * 8;
    int b_row = (lane & 7) + ((lane >> 4) & 1) * 8, b_k = ((lane >> 3) & 1) * 8;
    int v_row = (lane & 7) + ((lane >> 3) & 1) * 8, v_d = (lane >> 4) * 8;

    int c1r = tid >> 3, c1g = tid & 7;
    auto pfkv = [&](int t, int st) {
        int s0 = t * 128;
        #pragma unroll
        for (int i = 0; i < 4; i++) {
            int r = c1r + 32 * i;
            uint32_t o = (uint32_t)((st*KSTG + r*72 + c1g*8) * 2);
            size_t g = base + (size_t)(s0 + r) * CC + c1g*8;
            cpa16(sKh + o, Kh_ + g);
            cpa16(sKl + o, Kl_ + g);
            cpa16(sVs + o, V_ + g);
        }
        cpcommit();
    };
    pfkv(0, 0);

    uint32_t qfh[4][4], qfl[4][4];
    #pragma unroll
    for (int pass = 0; pass < 2; pass++) {
        const __half* src = pass ? Ql_ : Qh_;
        #pragma unroll
        for (int i = 0; i < 4; i++) {
            int c = tid + 256 * i;
            int row = c >> 3, cg = c & 7;
            *(uint4*)(Ph + row*PP + cg*8) =
                *(const uint4*)(src + base + (size_t)(r0 + row) * CC + cg*8);
        }
        __syncthreads();
        #pragma unroll
        for (int kt = 0; kt < 4; kt++) {
            uint32_t ad = sPh + (uint32_t)(((16*warp + a_row)*PP + kt*16 + a_k) * 2);
            if (pass) { LDM_X4(qfl[kt][0], qfl[kt][1], qfl[kt][2], qfl[kt][3], ad); }
            else      { LDM_X4(qfh[kt][0], qfh[kt][1], qfh[kt][2], qfh[kt][3], ad); }
        }
        __syncthreads();
    }

    float oacc[8][4];
    #pragma unroll
    for (int dj = 0; dj < 8; dj++)
        #pragma unroll
        for (int f = 0; f < 4; f++) oacc[dj][f] = 0.f;
    float m0 = -3e38f, m1 = -3e38f, l0 = 0.f, l1 = 0.f;

    const int NTL = TT / 128;   // 16
    for (int t = 0; t < NTL; t++) {
        int st = t & 1;
        cpwait<0>();
        __syncthreads();
        if (t + 1 < NTL) pfkv(t + 1, st ^ 1);

        float s[16][4];
        #pragma unroll
        for (int nj = 0; nj < 16; nj++)
            #pragma unroll
            for (int f = 0; f < 4; f++) s[nj][f] = 0.f;
        #pragma unroll
        for (int kt = 0; kt < 4; kt++) {
            #pragma unroll
            for (int nb = 0; nb < 8; nb++) {
                uint32_t off = (uint32_t)((st*KSTG + (nb*16 + b_row)*72
                                           + kt*16 + b_k) * 2);
                uint32_t h0,h1,h2,h3, e0,e1,e2,e3;
                LDM_X4(h0,h1,h2,h3, sKh + off);
                LDM_X4(e0,e1,e2,e3, sKl + off);
                int nj = nb * 2;
                MMA_F16(s[nj], qfh[kt][0],qfh[kt][1],qfh[kt][2],qfh[kt][3], e0,e1);
                MMA_F16(s[nj], qfl[kt][0],qfl[kt][1],qfl[kt][2],qfl[kt][3], h0,h1);
                MMA_F16(s[nj], qfh[kt][0],qfh[kt][1],qfh[kt][2],qfh[kt][3], h0,h1);
                MMA_F16(s[nj+1], qfh[kt][0],qfh[kt][1],qfh[kt][2],qfh[kt][3], e2,e3);
                MMA_F16(s[nj+1], qfl[kt][0],qfl[kt][1],qfl[kt][2],qfl[kt][3], h2,h3);
                MMA_F16(s[nj+1], qfh[kt][0],qfh[kt][1],qfh[kt][2],qfh[kt][3], h2,h3);
            }
        }
        // ---- online softmax (log2 domain: p = 2^(s-m)) ----
        float mt0 = -3e38f, mt1 = -3e38f;
        #pragma unroll
        for (int nj = 0; nj < 16; nj++) {
            mt0 = fmaxf(mt0, fmaxf(s[nj][0], s[nj][1]));
            mt1 = fmaxf(mt1, fmaxf(s[nj][2], s[nj][3]));
        }
        mt0 = fmaxf(mt0, __shfl_xor_sync(0xffffffffu, mt0, 1));
        mt0 = fmaxf(mt0, __shfl_xor_sync(0xffffffffu, mt0, 2));
        mt1 = fmaxf(mt1, __shfl_xor_sync(0xffffffffu, mt1, 1));
        mt1 = fmaxf(mt1, __shfl_xor_sync(0xffffffffu, mt1, 2));
        float mn0 = fmaxf(m0, mt0), mn1 = fmaxf(m1, mt1);
        float al0 = ex2f(m0 - mn0), al1 = ex2f(m1 - mn1);
        float ps0 = 0.f, ps1 = 0.f;
        int pr0 = (16*warp + lr) * PP, pr1 = (16*warp + 8 + lr) * PP;
        #pragma unroll
        for (int nj = 0; nj < 16; nj++) {
            float p0 = ex2f(s[nj][0] - mn0);
            float p1 = ex2f(s[nj][1] - mn0);
            float p2 = ex2f(s[nj][2] - mn1);
            float p3 = ex2f(s[nj][3] - mn1);
            ps0 += p0 + p1; ps1 += p2 + p3;
            *(half2*)(Ph + pr0 + nj*8 + 2*lc) = __floats2half2_rn(p0, p1);
            *(half2*)(Ph + pr1 + nj*8 + 2*lc) = __floats2half2_rn(p2, p3);
        }
        ps0 += __shfl_xor_sync(0xffffffffu, ps0, 1);
        ps0 += __shfl_xor_sync(0xffffffffu, ps0, 2);
        ps1 += __shfl_xor_sync(0xffffffffu, ps1, 1);
        ps1 += __shfl_xor_sync(0xffffffffu, ps1, 2);
        l0 = l0 * al0 + ps0;
        l1 = l1 * al1 + ps1;
        m0 = mn0; m1 = mn1;
        #pragma unroll
        for (int dj = 0; dj < 8; dj++) {
            oacc[dj][0] *= al0; oacc[dj][1] *= al0;
            oacc[dj][2] *= al1; oacc[dj][3] *= al1;
        }
        __syncwarp();
        #pragma unroll
        for (int kt = 0; kt < 8; kt++) {
            uint32_t pa0,pa1,pa2,pa3;
            LDM_X4(pa0,pa1,pa2,pa3,
                   sPh + (uint32_t)(((16*warp + a_row)*PP + kt*16 + a_k) * 2));
            #pragma unroll
            for (int dp = 0; dp < 4; dp++) {
                uint32_t v0,v1,v2,v3;
                uint32_t ad = sVs + (uint32_t)((st*KSTG + (kt*16 + v_row)*72
                                                + dp*16 + v_d) * 2);
                LDM_X4T(v0,v1,v2,v3, ad);
                MMA_F16(oacc[dp*2],   pa0,pa1,pa2,pa3, v0,v1);
                MMA_F16(oacc[dp*2+1], pa0,pa1,pa2,pa3, v2,v3);
            }
        }
    }
    float inv0 = 1.f / l0, inv1 = 1.f / l1;
    int row0 = r0 + 16*warp + lr, row1 = row0 + 8;
    #pragma unroll
    for (int dj = 0; dj < 8; dj++) {
        int col = dj*8 + 2*lc;
        *(half2*)(O_ + base + (size_t)row0 * CC + col) =
            __floats2half2_rn(oacc[dj][0]*inv0, oacc[dj][1]*inv0);
        *(half2*)(O_ + base + (size_t)row1 * CC + col) =
            __floats2half2_rn(oacc[dj][2]*inv1, oacc[dj][3]*inv1);
    }
}

// ========================= launch =========================
extern "C" void kernel_launch(void* const* d_in, const int* in_sizes, int n_in,
                              void* d_out, int out_size) {
    const float* x     = (const float*)d_in[0];
    const float* Wq    = (const float*)d_in[1];
    const float* bq    = (const float*)d_in[2];
    const float* Wk    = (const float*)d_in[3];
    const float* bk    = (const float*)d_in[4];
    const float* Wv    = (const float*)d_in[5];
    const float* bv    = (const float*)d_in[6];
    const float* Wo    = (const float*)d_in[7];
    const float* bo    = (const float*)d_in[8];
    const float* ln1g  = (const float*)d_in[9];
    const float* ln1b  = (const float*)d_in[10];
    const float* ln2g  = (const float*)d_in[11];
    const float* ln2b  = (const float*)d_in[12];
    const float* W1    = (const float*)d_in[13];
    const float* b1    = (const float*)d_in[14];
    const float* W2    = (const float*)d_in[15];
    const float* b2    = (const float*)d_in[16];
    float* out = (float*)d_out;

    __half *xnh,*xnl,*qh,*ql,*kh,*kl,*vh,*oh,*x2h,*ffh,*wqh,*wql,*wot,*w1t,*w2t;
    float *x1;
    cudaGetSymbolAddress((void**)&xnh, g_xnh);
    cudaGetSymbolAddress((void**)&xnl, g_xnl);
    cudaGetSymbolAddress((void**)&qh,  g_qhh);
    cudaGetSymbolAddress((void**)&ql,  g_qll);
    cudaGetSymbolAddress((void**)&kh,  g_khh);
    cudaGetSymbolAddress((void**)&kl,  g_kll);
    cudaGetSymbolAddress((void**)&vh,  g_vhh);
    cudaGetSymbolAddress((void**)&oh,  g_ohh);
    cudaGetSymbolAddress((void**)&x2h, g_x2h);
    cudaGetSymbolAddress((void**)&ffh, g_ffh);
    cudaGetSymbolAddress((void**)&x1,  g_x1);
    cudaGetSymbolAddress((void**)&wqh, g_wqh);
    cudaGetSymbolAddress((void**)&wql, g_wql);
    cudaGetSymbolAddress((void**)&wot, g_wot);
    cudaGetSymbolAddress((void**)&w1t, g_w1t);
    cudaGetSymbolAddress((void**)&w2t, g_w2t);

    cudaFuncSetAttribute(gemm_qkv_h, cudaFuncAttributeMaxDynamicSharedMemorySize, QKV_SMEM);
    cudaFuncSetAttribute(attn_h, cudaFuncAttributeMaxDynamicSharedMemorySize, ATSMH);
    cudaFuncSetAttribute(gemm_h<false,true,false>,
                         cudaFuncAttributeMaxDynamicSharedMemorySize, G_SMEM);
    cudaFuncSetAttribute(gemm_h<true,false,true>,
                         cudaFuncAttributeMaxDynamicSharedMemorySize, G_SMEM);

    // weight prep
    prep_qkv_h<<<dim3(16, 48), 256>>>(Wq, Wk, Wv, wqh, wql);
    prep_t<<<dim3(16, 16), 256>>>(Wo, wot, 1024, 1024);
    prep_t<<<dim3(64, 16), 256>>>(W1, w1t, 1024, 4096);
    prep_t<<<dim3(16, 64), 256>>>(W2, w2t, 4096, 1024);

    // 1) LN1 (hi+lo fp16)
    ln_h<2><<<MM, 256>>>(x, ln1g, ln1b, xnh, xnl);
    // 2) QKV (3-term fp16, S=3)
    gemm_qkv_h<<<dim3(24, 64), 256, QKV_SMEM>>>(xnh, xnl, wqh, wql,
                                                bq, bk, bv, qh, ql, kh, kl, vh);
    // 3) attention (fp16 TC flash, BC=128, log2 softmax)
    attn_h<<<dim3(TT/128, HH, BB), 256, ATSMH>>>(qh, ql, kh, kl, vh, oh);
    // 4) out proj + residual -> x1 (fp32)
    gemm_h<false, true, false><<<dim3(8, 64), 256, G_SMEM>>>(oh, wot, bo, x, (void*)x1, MM, CC, CC);
    // 5) LN2 (fp16 hi)
    ln_h<1><<<MM, 256>>>(x1, ln2g, ln2b, x2h, nullptr);
    // 6) FFN1 (relu, fp16 out)
    gemm_h<true, false, true><<<dim3(32, 64), 256, G_SMEM>>>(x2h, w1t, b1, nullptr, (void*)ffh, MM, DFF, CC);
    // 7) FFN2 + residual -> out (fp32)
    gemm_h<false, true, false><<<dim3(8, 64), 256, G_SMEM>>>(ffh, w2t, b2, x1, (void*)out, MM, CC, DFF);
}

// round 12
// speedup vs baseline: 1.0740x; 1.0740x over previous
#include <cuda_runtime.h>
#include <cuda_fp16.h>
#include <math.h>
#include <stdint.h>

#define BB 4
#define TT 2048
#define CC 1024
#define HH 16
#define DHH 64
#define DFF 4096
#define MM (BB*TT)   /* 8192 */

// -------- scratch (device globals; no allocation) --------
__device__ __half g_xnh[(size_t)MM*CC];
__device__ __half g_xnl[(size_t)MM*CC];
__device__ __half g_qhh[(size_t)MM*CC];
__device__ __half g_qll[(size_t)MM*CC];
__device__ __half g_khh[(size_t)MM*CC];
__device__ __half g_kll[(size_t)MM*CC];
__device__ __half g_vhh[(size_t)MM*CC];
__device__ __half g_ohh[(size_t)MM*CC];
__device__ __half g_x2h[(size_t)MM*CC];
__device__ __half g_ffh[(size_t)MM*DFF];
__device__ float  g_x1 [(size_t)MM*CC];
__device__ __half g_wqh[(size_t)CC*3072];
__device__ __half g_wql[(size_t)CC*3072];
__device__ __half g_wot[(size_t)CC*CC];
__device__ __half g_w1t[(size_t)CC*DFF];
__device__ __half g_w2t[(size_t)DFF*CC];

// ======================= helpers =======================
__device__ __forceinline__ uint32_t smem_u32(const void* p) {
    return (uint32_t)__cvta_generic_to_shared(p);
}
__device__ __forceinline__ float ex2f(float x) {
    float r;
    asm("ex2.approx.f32 %0, %1;" : "=f"(r) : "f"(x));
    return r;
}
#define LDM_X4(r0,r1,r2,r3, addr) \
    asm volatile("ldmatrix.sync.aligned.m8n8.x4.shared.b16 {%0,%1,%2,%3},[%4];" \
        : "=r"(r0),"=r"(r1),"=r"(r2),"=r"(r3) : "r"(addr))
#define LDM_X4T(r0,r1,r2,r3, addr) \
    asm volatile("ldmatrix.sync.aligned.m8n8.x4.trans.shared.b16 {%0,%1,%2,%3},[%4];" \
        : "=r"(r0),"=r"(r1),"=r"(r2),"=r"(r3) : "r"(addr))
#define MMA_F16(d, a0,a1,a2,a3, b0,b1) \
    asm volatile("mma.sync.aligned.m16n8k16.row.col.f32.f16.f16.f32 " \
        "{%0,%1,%2,%3},{%4,%5,%6,%7},{%8,%9},{%0,%1,%2,%3};" \
        : "+f"(d[0]),"+f"(d[1]),"+f"(d[2]),"+f"(d[3]) \
        : "r"(a0),"r"(a1),"r"(a2),"r"(a3),"r"(b0),"r"(b1))

__device__ __forceinline__ void cpa16(uint32_t dst, const void* src) {
    asm volatile("cp.async.cg.shared.global [%0], [%1], 16;\n" :: "r"(dst), "l"(src));
}
__device__ __forceinline__ void cpcommit() { asm volatile("cp.async.commit_group;\n" ::); }
template<int N> __device__ __forceinline__ void cpwait() {
    asm volatile("cp.async.wait_group %0;\n" :: "n"(N));
}

// ======================= prep kernels =======================
// Wqkv [H][C][DH] -> Th/Tl [n=3072][k=1024], vectorized 64x64 transpose
__global__ void prep_qkv_h(const float* __restrict__ Wq, const float* __restrict__ Wk,
                           const float* __restrict__ Wv,
                           __half* __restrict__ Th, __half* __restrict__ Tl) {
    __shared__ float t[64][65];
    int k0 = blockIdx.x * 64;
    int nt = blockIdx.y;                 // 0..47
    int mat = nt >> 4, h = nt & 15;
    const float* W = (mat == 0) ? Wq : (mat == 1) ? Wk : Wv;
    int tid = threadIdx.x;
    int ty = tid >> 4, tx = tid & 15;
    #pragma unroll
    for (int j = 0; j < 4; j++) {
        int ky = ty + 16 * j;
        float4 v = *(const float4*)(W + h * 65536 + (size_t)(k0 + ky) * 64 + tx * 4);
        t[ky][tx*4+0] = v.x; t[ky][tx*4+1] = v.y;
        t[ky][tx*4+2] = v.z; t[ky][tx*4+3] = v.w;
    }
    __syncthreads();
    int nr = tid >> 2, kc = (tid & 3) * 16;
    __half hh[16], hl[16];
    #pragma unroll
    for (int i = 0; i < 16; i++) {
        float w = t[kc + i][nr];
        __half hi = __float2half_rn(w);
        hh[i] = hi;
        hl[i] = __float2half_rn(w - __half2float(hi));
    }
    size_t n = (size_t)(mat * 1024 + h * 64 + nr);
    uint4* dh = (uint4*)(Th + n * CC + k0 + kc);
    uint4* dl = (uint4*)(Tl + n * CC + k0 + kc);
    dh[0] = *(uint4*)&hh[0]; dh[1] = *(uint4*)&hh[8];
    dl[0] = *(uint4*)&hl[0]; dl[1] = *(uint4*)&hl[8];
}

// W[K][N] f32 -> Wt[N][K] fp16, 64x64 tiles (validated R9: 2.1 TB/s)
__global__ void prep_t(const float* __restrict__ W, __half* __restrict__ Wt, int K, int N) {
    __shared__ float t[64][65];
    int n0 = blockIdx.x * 64, k0 = blockIdx.y * 64;
    int tid = threadIdx.x;
    int ty = tid >> 4, tx = tid & 15;
    #pragma unroll
    for (int j = 0; j < 4; j++) {
        float4 v = *(const float4*)(W + (size_t)(k0 + ty + 16*j) * N + n0 + tx*4);
        t[ty + 16*j][tx*4+0] = v.x; t[ty + 16*j][tx*4+1] = v.y;
        t[ty + 16*j][tx*4+2] = v.z; t[ty + 16*j][tx*4+3] = v.w;
    }
    __syncthreads();
    int nr = tid >> 2, kc = (tid & 3) * 16;
    __half h16[16];
    #pragma unroll
    for (int i = 0; i < 16; i++) h16[i] = __float2half_rn(t[kc + i][nr]);
    uint4* dst = (uint4*)(Wt + (size_t)(n0 + nr) * K + k0 + kc);
    dst[0] = *(uint4*)&h16[0];
    dst[1] = *(uint4*)&h16[8];
}

// ======================= LayerNorm (f32 in, fp16 out) =======================
template<int MODE>   // 2 = hi+lo, 1 = hi only
__global__ void ln_h(const float* __restrict__ X, const float* __restrict__ gam,
                     const float* __restrict__ bet,
                     __half* __restrict__ Yh, __half* __restrict__ Yl) {
    int row = blockIdx.x;
    const float* xr = X + (size_t)row * CC;
    int tid = threadIdx.x;
    float4 v = *(const float4*)(xr + tid * 4);
    float s  = v.x + v.y + v.z + v.w;
    float ss = v.x*v.x + v.y*v.y + v.z*v.z + v.w*v.w;
    #pragma unroll
    for (int off = 16; off >= 1; off >>= 1) {
        s  += __shfl_xor_sync(0xffffffffu, s,  off);
        ss += __shfl_xor_sync(0xffffffffu, ss, off);
    }
    __shared__ float sb[8], ssb[8];
    if ((tid & 31) == 0) { sb[tid >> 5] = s; ssb[tid >> 5] = ss; }
    __syncthreads();
    s = 0.f; ss = 0.f;
    #pragma unroll
    for (int w = 0; w < 8; w++) { s += sb[w]; ss += ssb[w]; }
    float mu  = s * (1.0f / CC);
    float var = ss * (1.0f / CC) - mu * mu;
    float rs  = rsqrtf(var + 1e-5f);
    float4 gv = *(const float4*)(gam + tid * 4);
    float4 bv = *(const float4*)(bet + tid * 4);
    float y[4];
    y[0] = (v.x - mu) * rs * gv.x + bv.x;
    y[1] = (v.y - mu) * rs * gv.y + bv.y;
    y[2] = (v.z - mu) * rs * gv.z + bv.z;
    y[3] = (v.w - mu) * rs * gv.w + bv.w;
    __half h[4];
    #pragma unroll
    for (int i = 0; i < 4; i++) h[i] = __float2half_rn(y[i]);
    int off = row * CC + tid * 4;
    half2 a = __halves2half2(h[0], h[1]);
    half2 b = __halves2half2(h[2], h[3]);
    uint2 u; u.x = *(uint32_t*)&a; u.y = *(uint32_t*)&b;
    *(uint2*)(Yh + off) = u;
    if (MODE == 2) {
        __half lo[4];
        #pragma unroll
        for (int i = 0; i < 4; i++) lo[i] = __float2half_rn(y[i] - __half2float(h[i]));
        half2 c = __halves2half2(lo[0], lo[1]);
        half2 d = __halves2half2(lo[2], lo[3]);
        uint2 w; w.x = *(uint32_t*)&c; w.y = *(uint32_t*)&d;
        *(uint2*)(Yl + off) = w;
    }
}

// ============ fp16 GEMM: 128x128x32 tiles, 4-stage pipeline, occ 2 (R10 config) ============
#define GP 40                 // smem pitch in halves
#define GST 5120              // stage stride in halves (128*40)
#define NSTG 4
#define G_SMEM (NSTG*GST*2*2) // 81920 bytes
template<bool RELU, bool RESID, bool OUTH>
__global__ __launch_bounds__(256, 2) void gemm_h(
        const __half* __restrict__ A, const __half* __restrict__ Bt,
        const float* __restrict__ bias, const float* __restrict__ resid,
        void* __restrict__ Cv, int M, int N, int K) {
    extern __shared__ __half gsm[];
    __half* As = gsm;                 // [NSTG][GST]
    __half* Bs = gsm + NSTG*GST;
    int tid = threadIdx.x, l = tid & 31, warp = tid >> 5;
    int wy = warp >> 2, wx = warp & 3, lr = l >> 2, lc = l & 3;
    int m0 = blockIdx.y * 128, n0 = blockIdx.x * 128;
    int a_row = (l & 7) + ((l >> 3) & 1) * 8, a_k = (l >> 4) * 8;
    int b_row = (l & 7) + ((l >> 4) & 1) * 8, b_k = ((l >> 3) & 1) * 8;
    float acc[4][4][4];
    #pragma unroll
    for (int i = 0; i < 4; i++)
        #pragma unroll
        for (int j = 0; j < 4; j++)
            #pragma unroll
            for (int f = 0; f < 4; f++) acc[i][j][f] = 0.f;
    uint32_t sA = smem_u32(As), sB = smem_u32(Bs);
    int r1c = tid >> 2, g1c = tid & 3;
    int r2c = (tid + 256) >> 2;
    const int NT = K >> 5;
    auto loadT = [&](int kt, int st) {
        int k0 = kt * 32;
        uint32_t o1 = (uint32_t)((st*GST + r1c*GP + g1c*8) * 2);
        uint32_t o2 = (uint32_t)((st*GST + r2c*GP + g1c*8) * 2);
        cpa16(sA + o1, A + (size_t)(m0 + r1c) * K + k0 + g1c*8);
        cpa16(sA + o2, A + (size_t)(m0 + r2c) * K + k0 + g1c*8);
        cpa16(sB + o1, Bt + (size_t)(n0 + r1c) * K + k0 + g1c*8);
        cpa16(sB + o2, Bt + (size_t)(n0 + r2c) * K + k0 + g1c*8);
        cpcommit();
    };
    loadT(0, 0);
    loadT(1, 1);
    loadT(2, 2);
    int st = 0, ldst = 3;
    for (int kt = 0; kt < NT; kt++) {
        cpwait<NSTG-2>();
        __syncthreads();
        if (kt + 3 < NT) {
            loadT(kt + 3, ldst);
            if (++ldst == NSTG) ldst = 0;
        }
        #pragma unroll
        for (int ks = 0; ks < 2; ks++) {
            uint32_t af[4][4], bf[4][2];
            #pragma unroll
            for (int mi = 0; mi < 4; mi++) {
                uint32_t ad = sA + (uint32_t)((st*GST + (wy*64 + mi*16 + a_row)*GP
                                               + ks*16 + a_k) * 2);
                LDM_X4(af[mi][0], af[mi][1], af[mi][2], af[mi][3], ad);
            }
            #pragma unroll
            for (int nb = 0; nb < 2; nb++) {
                uint32_t ad = sB + (uint32_t)((st*GST + (wx*32 + nb*16 + b_row)*GP
                                               + ks*16 + b_k) * 2);
                uint32_t q0,q1,q2,q3;
                LDM_X4(q0,q1,q2,q3, ad);
                bf[nb*2][0]=q0; bf[nb*2][1]=q1; bf[nb*2+1][0]=q2; bf[nb*2+1][1]=q3;
            }
            #pragma unroll
            for (int mi = 0; mi < 4; mi++)
                #pragma unroll
                for (int nj = 0; nj < 4; nj++)
                    MMA_F16(acc[mi][nj], af[mi][0],af[mi][1],af[mi][2],af[mi][3],
                            bf[nj][0], bf[nj][1]);
        }
        if (++st == NSTG) st = 0;
    }
    #pragma unroll
    for (int mi = 0; mi < 4; mi++) {
        #pragma unroll
        for (int nj = 0; nj < 4; nj++) {
            int row = m0 + wy*64 + mi*16 + lr;
            int col = n0 + wx*32 + nj*8 + 2*lc;
            float b0 = bias[col], b1 = bias[col+1];
            float v0 = acc[mi][nj][0] + b0, v1 = acc[mi][nj][1] + b1;
            float v2 = acc[mi][nj][2] + b0, v3 = acc[mi][nj][3] + b1;
            if (RESID) {
                float2 q0 = *(const float2*)(resid + (size_t)row * N + col);
                float2 q1 = *(const float2*)(resid + (size_t)(row+8) * N + col);
                v0 += q0.x; v1 += q0.y; v2 += q1.x; v3 += q1.y;
            }
            if (RELU) {
                v0 = fmaxf(v0, 0.f); v1 = fmaxf(v1, 0.f);
                v2 = fmaxf(v2, 0.f); v3 = fmaxf(v3, 0.f);
            }
            if (OUTH) {
                __half* C = (__half*)Cv;
                *(half2*)(C + (size_t)row * N + col)     = __floats2half2_rn(v0, v1);
                *(half2*)(C + (size_t)(row+8) * N + col) = __floats2half2_rn(v2, v3);
            } else {
                float* C = (float*)Cv;
                *(float2*)(C + (size_t)row * N + col)     = make_float2(v0, v1);
                *(float2*)(C + (size_t)(row+8) * N + col) = make_float2(v2, v3);
            }
        }
    }
}

// ============ QKV GEMM: 3-term fp16 split, S=2 single-sync (R10 config) ============
#define QST 5120
#define QKV_SMEM (2*QST*4*2)   // 81920 B
__global__ __launch_bounds__(256) void gemm_qkv_h(
        const __half* __restrict__ Ah_, const __half* __restrict__ Al_,
        const __half* __restrict__ Bh_, const __half* __restrict__ Bl_,
        const float* __restrict__ bq, const float* __restrict__ bk_,
        const float* __restrict__ bv_,
        __half* __restrict__ qh, __half* __restrict__ ql,
        __half* __restrict__ kh, __half* __restrict__ kl,
        __half* __restrict__ vh) {
    extern __shared__ __half smq[];
    __half* Ah = smq;            // [2][5120]
    __half* Al = smq + 10240;
    __half* Bh = smq + 20480;
    __half* Bl = smq + 30720;
    const int K = CC;
    int tid = threadIdx.x, l = tid & 31, warp = tid >> 5;
    int wy = warp >> 2, wx = warp & 3, lr = l >> 2, lc = l & 3;
    int m0 = blockIdx.y * 128, n0 = blockIdx.x * 128;
    int a_row = (l & 7) + ((l >> 3) & 1) * 8, a_k = (l >> 4) * 8;
    int b_row = (l & 7) + ((l >> 4) & 1) * 8, b_k = ((l >> 3) & 1) * 8;
    float acc[4][4][4];
    #pragma unroll
    for (int i = 0; i < 4; i++)
        #pragma unroll
        for (int j = 0; j < 4; j++)
            #pragma unroll
            for (int f = 0; f < 4; f++) acc[i][j][f] = 0.f;
    uint32_t sAh = smem_u32(Ah), sAl = smem_u32(Al);
    uint32_t sBh = smem_u32(Bh), sBl = smem_u32(Bl);
    int r1c = tid >> 2, g1c = tid & 3;
    int r2c = (tid + 256) >> 2;
    const int NT = K >> 5;
    auto pf = [&](int kt, int st) {
        int k0 = kt * 32;
        uint32_t o1 = (uint32_t)((st*QST + r1c*GP + g1c*8) * 2);
        uint32_t o2 = (uint32_t)((st*QST + r2c*GP + g1c*8) * 2);
        cpa16(sAh + o1, Ah_ + (size_t)(m0 + r1c) * K + k0 + g1c*8);
        cpa16(sAh + o2, Ah_ + (size_t)(m0 + r2c) * K + k0 + g1c*8);
        cpa16(sBh + o1, Bh_ + (size_t)(n0 + r1c) * K + k0 + g1c*8);
        cpa16(sBh + o2, Bh_ + (size_t)(n0 + r2c) * K + k0 + g1c*8);
        cpa16(sAl + o1, Al_ + (size_t)(m0 + r1c) * K + k0 + g1c*8);
        cpa16(sAl + o2, Al_ + (size_t)(m0 + r2c) * K + k0 + g1c*8);
        cpa16(sBl + o1, Bl_ + (size_t)(n0 + r1c) * K + k0 + g1c*8);
        cpa16(sBl + o2, Bl_ + (size_t)(n0 + r2c) * K + k0 + g1c*8);
        cpcommit();
    };
    pf(0, 0);
    for (int kt = 0; kt < NT; kt++) {
        int st = kt & 1;
        cpwait<0>();
        __syncthreads();
        if (kt + 1 < NT) pf(kt + 1, st ^ 1);
        #pragma unroll
        for (int ks = 0; ks < 2; ks++) {
            uint32_t afh[4][4], afl[4][4];
            #pragma unroll
            for (int mi = 0; mi < 4; mi++) {
                uint32_t ao = (uint32_t)((st*QST + (wy*64 + mi*16 + a_row)*GP
                                          + ks*16 + a_k) * 2);
                LDM_X4(afh[mi][0], afh[mi][1], afh[mi][2], afh[mi][3], sAh + ao);
                LDM_X4(afl[mi][0], afl[mi][1], afl[mi][2], afl[mi][3], sAl + ao);
            }
            #pragma unroll
            for (int nb = 0; nb < 2; nb++) {
                uint32_t bo = (uint32_t)((st*QST + (wx*32 + nb*16 + b_row)*GP
                                          + ks*16 + b_k) * 2);
                uint32_t h0,h1,h2,h3, e0,e1,e2,e3;
                LDM_X4(h0,h1,h2,h3, sBh + bo);
                LDM_X4(e0,e1,e2,e3, sBl + bo);
                #pragma unroll
                for (int mi = 0; mi < 4; mi++) {
                    int nj = nb * 2;
                    MMA_F16(acc[mi][nj], afh[mi][0],afh[mi][1],afh[mi][2],afh[mi][3], e0,e1);
                    MMA_F16(acc[mi][nj], afl[mi][0],afl[mi][1],afl[mi][2],afl[mi][3], h0,h1);
                    MMA_F16(acc[mi][nj], afh[mi][0],afh[mi][1],afh[mi][2],afh[mi][3], h0,h1);
                    MMA_F16(acc[mi][nj+1], afh[mi][0],afh[mi][1],afh[mi][2],afh[mi][3], e2,e3);
                    MMA_F16(acc[mi][nj+1], afl[mi][0],afl[mi][1],afl[mi][2],afl[mi][3], h2,h3);
                    MMA_F16(acc[mi][nj+1], afh[mi][0],afh[mi][1],afh[mi][2],afh[mi][3], h2,h3);
                }
            }
        }
    }
    int mat = n0 >> 10, rem0 = n0 & 1023;
    const float* bias = (mat == 0) ? bq : (mat == 1) ? bk_ : bv_;
    // Q scaled by 8*log2(e): softmax runs in log2 domain
    float sc = (mat == 0) ? 8.0f * 1.4426950408889634f : 1.f;
    #pragma unroll
    for (int mi = 0; mi < 4; mi++) {
        #pragma unroll
        for (int nj = 0; nj < 4; nj++) {
            int row = m0 + wy*64 + mi*16 + lr;
            int col = rem0 + wx*32 + nj*8 + 2*lc;
            float b0 = bias[col], b1 = bias[col+1];
            float v0 = (acc[mi][nj][0] + b0) * sc, v1 = (acc[mi][nj][1] + b1) * sc;
            float v2 = (acc[mi][nj][2] + b0) * sc, v3 = (acc[mi][nj][3] + b1) * sc;
            size_t i0 = (size_t)row * CC + col, i1 = (size_t)(row+8) * CC + col;
            if (mat == 2) {
                *(half2*)(vh + i0) = __floats2half2_rn(v0, v1);
                *(half2*)(vh + i1) = __floats2half2_rn(v2, v3);
            } else {
                __half* oh = (mat == 0) ? qh : kh;
                __half* ol = (mat == 0) ? ql : kl;
                __half h0 = __float2half_rn(v0), h1 = __float2half_rn(v1);
                __half h2 = __float2half_rn(v2), h3 = __float2half_rn(v3);
                *(half2*)(oh + i0) = __halves2half2(h0, h1);
                *(half2*)(oh + i1) = __halves2half2(h2, h3);
                *(half2*)(ol + i0) = __halves2half2(
                    __float2half_rn(v0 - __half2float(h0)),
                    __float2half_rn(v1 - __half2float(h1)));
                *(half2*)(ol + i1) = __halves2half2(
                    __float2half_rn(v2 - __half2float(h2)),
                    __float2half_rn(v3 - __half2float(h3)));
            }
        }
    }
}

// ================= fp16 flash attention, BC=128, log2-domain softmax =================
#define PP 136
#define KSTG 9216
#define ATSMH (72704*2)
__global__ __launch_bounds__(256, 1) void attn_h(
        const __half* __restrict__ Qh_, const __half* __restrict__ Ql_,
        const __half* __restrict__ Kh_, const __half* __restrict__ Kl_,
        const __half* __restrict__ V_, __half* __restrict__ O_) {
    extern __shared__ __half sma[];
    __half* Ph = sma;
    __half* Kh = sma + 17408;
    __half* Kl = sma + 35840;
    __half* Vs = sma + 54272;
    uint32_t sPh = smem_u32(Ph), sKh = smem_u32(Kh), sKl = smem_u32(Kl), sVs = smem_u32(Vs);
    int tid = threadIdx.x, lane = tid & 31, warp = tid >> 5;
    int lr = lane >> 2, lc = lane & 3;
    int r0 = blockIdx.x * 128;
    int h  = blockIdx.y;
    int b  = blockIdx.z;
    size_t base = (size_t)b * TT * CC + h * DHH;

    int a_row = (lane & 7) + ((lane >> 3) & 1) * 8, a_k = (lane >> 4) * 8;
    int b_row = (lane & 7) + ((lane >> 4) & 1) * 8, b_k = ((lane >> 3) & 1) * 8;
    int v_row = (lane & 7) + ((lane >> 3) & 1) * 8, v_d = (lane >> 4) * 8;

    int c1r = tid >> 3, c1g = tid & 7;
    auto pfkv = [&](int t, int st) {
        int s0 = t * 128;
        #pragma unroll
        for (int i = 0; i < 4; i++) {
            int r = c1r + 32 * i;
            uint32_t o = (uint32_t)((st*KSTG + r*72 + c1g*8) * 2);
            size_t g = base + (size_t)(s0 + r) * CC + c1g*8;
            cpa16(sKh + o, Kh_ + g);
            cpa16(sKl + o, Kl_ + g);
            cpa16(sVs + o, V_ + g);
        }
        cpcommit();
    };
    pfkv(0, 0);

    uint32_t qfh[4][4], qfl[4][4];
    #pragma unroll
    for (int pass = 0; pass < 2; pass++) {
        const __half* src = pass ? Ql_ : Qh_;
        #pragma unroll
        for (int i = 0; i < 4; i++) {
            int c = tid + 256 * i;
            int row = c >> 3, cg = c & 7;
            *(uint4*)(Ph + row*PP + cg*8) =
                *(const uint4*)(src + base + (size_t)(r0 + row) * CC + cg*8);
        }
        __syncthreads();
        #pragma unroll
        for (int kt = 0; kt < 4; kt++) {
            uint32_t ad = sPh + (uint32_t)(((16*warp + a_row)*PP + kt*16 + a_k) * 2);
            if (pass) { LDM_X4(qfl[kt][0], qfl[kt][1], qfl[kt][2], qfl[kt][3], ad); }
            else      { LDM_X4(qfh[kt][0], qfh[kt][1], qfh[kt][2], qfh[kt][3], ad); }
        }
        __syncthreads();
    }

    float oacc[8][4];
    #pragma unroll
    for (int dj = 0; dj < 8; dj++)
        #pragma unroll
        for (int f = 0; f < 4; f++) oacc[dj][f] = 0.f;
    float m0 = -3e38f, m1 = -3e38f, l0 = 0.f, l1 = 0.f;

    const int NTL = TT / 128;   // 16
    for (int t = 0; t < NTL; t++) {
        int st = t & 1;
        cpwait<0>();
        __syncthreads();
        if (t + 1 < NTL) pfkv(t + 1, st ^ 1);

        float s[16][4];
        #pragma unroll
        for (int nj = 0; nj < 16; nj++)
            #pragma unroll
            for (int f = 0; f < 4; f++) s[nj][f] = 0.f;
        #pragma unroll
        for (int kt = 0; kt < 4; kt++) {
            #pragma unroll
            for (int nb = 0; nb < 8; nb++) {
                uint32_t off = (uint32_t)((st*KSTG + (nb*16 + b_row)*72
                                           + kt*16 + b_k) * 2);
                uint32_t h0,h1,h2,h3, e0,e1,e2,e3;
                LDM_X4(h0,h1,h2,h3, sKh + off);
                LDM_X4(e0,e1,e2,e3, sKl + off);
                int nj = nb * 2;
                MMA_F16(s[nj], qfh[kt][0],qfh[kt][1],qfh[kt][2],qfh[kt][3], e0,e1);
                MMA_F16(s[nj], qfl[kt][0],qfl[kt][1],qfl[kt][2],qfl[kt][3], h0,h1);
                MMA_F16(s[nj], qfh[kt][0],qfh[kt][1],qfh[kt][2],qfh[kt][3], h0,h1);
                MMA_F16(s[nj+1], qfh[kt][0],qfh[kt][1],qfh[kt][2],qfh[kt][3], e2,e3);
                MMA_F16(s[nj+1], qfl[kt][0],qfl[kt][1],qfl[kt][2],qfl[kt][3], h2,h3);
                MMA_F16(s[nj+1], qfh[kt][0],qfh[kt][1],qfh[kt][2],qfh[kt][3], h2,h3);
            }
        }
        // ---- online softmax (log2 domain: p = 2^(s-m)) ----
        float mt0 = -3e38f, mt1 = -3e38f;
        #pragma unroll
        for (int nj = 0; nj < 16; nj++) {
            mt0 = fmaxf(mt0, fmaxf(s[nj][0], s[nj][1]));
            mt1 = fmaxf(mt1, fmaxf(s[nj][2], s[nj][3]));
        }
        mt0 = fmaxf(mt0, __shfl_xor_sync(0xffffffffu, mt0, 1));
        mt0 = fmaxf(mt0, __shfl_xor_sync(0xffffffffu, mt0, 2));
        mt1 = fmaxf(mt1, __shfl_xor_sync(0xffffffffu, mt1, 1));
        mt1 = fmaxf(mt1, __shfl_xor_sync(0xffffffffu, mt1, 2));
        float mn0 = fmaxf(m0, mt0), mn1 = fmaxf(m1, mt1);
        float al0 = ex2f(m0 - mn0), al1 = ex2f(m1 - mn1);
        float ps0 = 0.f, ps1 = 0.f;
        int pr0 = (16*warp + lr) * PP, pr1 = (16*warp + 8 + lr) * PP;
        #pragma unroll
        for (int nj = 0; nj < 16; nj++) {
            float p0 = ex2f(s[nj][0] - mn0);
            float p1 = ex2f(s[nj][1] - mn0);
            float p2 = ex2f(s[nj][2] - mn1);
            float p3 = ex2f(s[nj][3] - mn1);
            ps0 += p0 + p1; ps1 += p2 + p3;
            *(half2*)(Ph + pr0 + nj*8 + 2*lc) = __floats2half2_rn(p0, p1);
            *(half2*)(Ph + pr1 + nj*8 + 2*lc) = __floats2half2_rn(p2, p3);
        }
        ps0 += __shfl_xor_sync(0xffffffffu, ps0, 1);
        ps0 += __shfl_xor_sync(0xffffffffu, ps0, 2);
        ps1 += __shfl_xor_sync(0xffffffffu, ps1, 1);
        ps1 += __shfl_xor_sync(0xffffffffu, ps1, 2);
        l0 = l0 * al0 + ps0;
        l1 = l1 * al1 + ps1;
        m0 = mn0; m1 = mn1;
        #pragma unroll
        for (int dj = 0; dj < 8; dj++) {
            oacc[dj][0] *= al0; oacc[dj][1] *= al0;
            oacc[dj][2] *= al1; oacc[dj][3] *= al1;
        }
        __syncwarp();
        #pragma unroll
        for (int kt = 0; kt < 8; kt++) {
            uint32_t pa0,pa1,pa2,pa3;
            LDM_X4(pa0,pa1,pa2,pa3,
                   sPh + (uint32_t)(((16*warp + a_row)*PP + kt*16 + a_k) * 2));
            #pragma unroll
            for (int dp = 0; dp < 4; dp++) {
                uint32_t v0,v1,v2,v3;
                uint32_t ad = sVs + (uint32_t)((st*KSTG + (kt*16 + v_row)*72
                                                + dp*16 + v_d) * 2);
                LDM_X4T(v0,v1,v2,v3, ad);
                MMA_F16(oacc[dp*2],   pa0,pa1,pa2,pa3, v0,v1);
                MMA_F16(oacc[dp*2+1], pa0,pa1,pa2,pa3, v2,v3);
            }
        }
    }
    float inv0 = 1.f / l0, inv1 = 1.f / l1;
    int row0 = r0 + 16*warp + lr, row1 = row0 + 8;
    #pragma unroll
    for (int dj = 0; dj < 8; dj++) {
        int col = dj*8 + 2*lc;
        *(half2*)(O_ + base + (size_t)row0 * CC + col) =
            __floats2half2_rn(oacc[dj][0]*inv0, oacc[dj][1]*inv0);
        *(half2*)(O_ + base + (size_t)row1 * CC + col) =
            __floats2half2_rn(oacc[dj][2]*inv1, oacc[dj][3]*inv1);
    }
}

// ========================= launch =========================
extern "C" void kernel_launch(void* const* d_in, const int* in_sizes, int n_in,
                              void* d_out, int out_size) {
    const float* x     = (const float*)d_in[0];
    const float* Wq    = (const float*)d_in[1];
    const float* bq    = (const float*)d_in[2];
    const float* Wk    = (const float*)d_in[3];
    const float* bk    = (const float*)d_in[4];
    const float* Wv    = (const float*)d_in[5];
    const float* bv    = (const float*)d_in[6];
    const float* Wo    = (const float*)d_in[7];
    const float* bo    = (const float*)d_in[8];
    const float* ln1g  = (const float*)d_in[9];
    const float* ln1b  = (const float*)d_in[10];
    const float* ln2g  = (const float*)d_in[11];
    const float* ln2b  = (const float*)d_in[12];
    const float* W1    = (const float*)d_in[13];
    const float* b1    = (const float*)d_in[14];
    const float* W2    = (const float*)d_in[15];
    const float* b2    = (const float*)d_in[16];
    float* out = (float*)d_out;

    __half *xnh,*xnl,*qh,*ql,*kh,*kl,*vh,*oh,*x2h,*ffh,*wqh,*wql,*wot,*w1t,*w2t;
    float *x1;
    cudaGetSymbolAddress((void**)&xnh, g_xnh);
    cudaGetSymbolAddress((void**)&xnl, g_xnl);
    cudaGetSymbolAddress((void**)&qh,  g_qhh);
    cudaGetSymbolAddress((void**)&ql,  g_qll);
    cudaGetSymbolAddress((void**)&kh,  g_khh);
    cudaGetSymbolAddress((void**)&kl,  g_kll);
    cudaGetSymbolAddress((void**)&vh,  g_vhh);
    cudaGetSymbolAddress((void**)&oh,  g_ohh);
    cudaGetSymbolAddress((void**)&x2h, g_x2h);
    cudaGetSymbolAddress((void**)&ffh, g_ffh);
    cudaGetSymbolAddress((void**)&x1,  g_x1);
    cudaGetSymbolAddress((void**)&wqh, g_wqh);
    cudaGetSymbolAddress((void**)&wql, g_wql);
    cudaGetSymbolAddress((void**)&wot, g_wot);
    cudaGetSymbolAddress((void**)&w1t, g_w1t);
    cudaGetSymbolAddress((void**)&w2t, g_w2t);

    cudaFuncSetAttribute(gemm_qkv_h, cudaFuncAttributeMaxDynamicSharedMemorySize, QKV_SMEM);
    cudaFuncSetAttribute(attn_h, cudaFuncAttributeMaxDynamicSharedMemorySize, ATSMH);
    cudaFuncSetAttribute(gemm_h<false,true,false>,
                         cudaFuncAttributeMaxDynamicSharedMemorySize, G_SMEM);
    cudaFuncSetAttribute(gemm_h<true,false,true>,
                         cudaFuncAttributeMaxDynamicSharedMemorySize, G_SMEM);

    // weight prep
    prep_qkv_h<<<dim3(16, 48), 256>>>(Wq, Wk, Wv, wqh, wql);
    prep_t<<<dim3(16, 16), 256>>>(Wo, wot, 1024, 1024);
    prep_t<<<dim3(64, 16), 256>>>(W1, w1t, 1024, 4096);
    prep_t<<<dim3(16, 64), 256>>>(W2, w2t, 4096, 1024);

    // 1) LN1 (hi+lo fp16)
    ln_h<2><<<MM, 256>>>(x, ln1g, ln1b, xnh, xnl);
    // 2) QKV (3-term fp16, S=2)
    gemm_qkv_h<<<dim3(24, 64), 256, QKV_SMEM>>>(xnh, xnl, wqh, wql,
                                                bq, bk, bv, qh, ql, kh, kl, vh);
    // 3) attention (fp16 TC flash, BC=128, log2 softmax)
    attn_h<<<dim3(TT/128, HH, BB), 256, ATSMH>>>(qh, ql, kh, kl, vh, oh);
    // 4) out proj + residual -> x1 (fp32)
    gemm_h<false, true, false><<<dim3(8, 64), 256, G_SMEM>>>(oh, wot, bo, x, (void*)x1, MM, CC, CC);
    // 5) LN2 (fp16 hi)
    ln_h<1><<<MM, 256>>>(x1, ln2g, ln2b, x2h, nullptr);
    // 6) FFN1 (relu, fp16 out)
    gemm_h<true, false, true><<<dim3(32, 64), 256, G_SMEM>>>(x2h, w1t, b1, nullptr, (void*)ffh, MM, DFF, CC);
    // 7) FFN2 + residual -> out (fp32)
    gemm_h<false, true, false><<<dim3(8, 64), 256, G_SMEM>>>(ffh, w2t, b2, x1, (void*)out, MM, CC, DFF);
}

// round 13
// speedup vs baseline: 1.0768x; 1.0027x over previous
#include <cuda_runtime.h>
#include <cuda_fp16.h>
#include <math.h>
#include <stdint.h>

#define BB 4
#define TT 2048
#define CC 1024
#define HH 16
#define DHH 64
#define DFF 4096
#define MM (BB*TT)   /* 8192 */

// -------- scratch (device globals; no allocation) --------
__device__ __half g_xnh[(size_t)MM*CC];
__device__ __half g_xnl[(size_t)MM*CC];
__device__ __half g_qhh[(size_t)MM*CC];
__device__ __half g_qll[(size_t)MM*CC];
__device__ __half g_khh[(size_t)MM*CC];
__device__ __half g_kll[(size_t)MM*CC];
__device__ __half g_vhh[(size_t)MM*CC];
__device__ __half g_ohh[(size_t)MM*CC];
__device__ __half g_x2h[(size_t)MM*CC];
__device__ __half g_ffh[(size_t)MM*DFF];
__device__ float  g_x1 [(size_t)MM*CC];
__device__ __half g_wqh[(size_t)CC*3072];
__device__ __half g_wql[(size_t)CC*3072];
__device__ __half g_wot[(size_t)CC*CC];
__device__ __half g_w1t[(size_t)CC*DFF];
__device__ __half g_w2t[(size_t)DFF*CC];

// ======================= helpers =======================
__device__ __forceinline__ uint32_t smem_u32(const void* p) {
    return (uint32_t)__cvta_generic_to_shared(p);
}
__device__ __forceinline__ float ex2f(float x) {
    float r;
    asm("ex2.approx.f32 %0, %1;" : "=f"(r) : "f"(x));
    return r;
}
#define LDM_X4(r0,r1,r2,r3, addr) \
    asm volatile("ldmatrix.sync.aligned.m8n8.x4.shared.b16 {%0,%1,%2,%3},[%4];" \
        : "=r"(r0),"=r"(r1),"=r"(r2),"=r"(r3) : "r"(addr))
#define LDM_X4T(r0,r1,r2,r3, addr) \
    asm volatile("ldmatrix.sync.aligned.m8n8.x4.trans.shared.b16 {%0,%1,%2,%3},[%4];" \
        : "=r"(r0),"=r"(r1),"=r"(r2),"=r"(r3) : "r"(addr))
#define MMA_F16(d, a0,a1,a2,a3, b0,b1) \
    asm volatile("mma.sync.aligned.m16n8k16.row.col.f32.f16.f16.f32 " \
        "{%0,%1,%2,%3},{%4,%5,%6,%7},{%8,%9},{%0,%1,%2,%3};" \
        : "+f"(d[0]),"+f"(d[1]),"+f"(d[2]),"+f"(d[3]) \
        : "r"(a0),"r"(a1),"r"(a2),"r"(a3),"r"(b0),"r"(b1))

__device__ __forceinline__ void cpa16(uint32_t dst, const void* src) {
    asm volatile("cp.async.cg.shared.global [%0], [%1], 16;\n" :: "r"(dst), "l"(src));
}
__device__ __forceinline__ void cpcommit() { asm volatile("cp.async.commit_group;\n" ::); }
template<int N> __device__ __forceinline__ void cpwait() {
    asm volatile("cp.async.wait_group %0;\n" :: "n"(N));
}

// ======================= prep kernels =======================
// Wqkv [H][C][DH] -> Th/Tl [n=3072][k=1024], vectorized 64x64 transpose
__global__ void prep_qkv_h(const float* __restrict__ Wq, const float* __restrict__ Wk,
                           const float* __restrict__ Wv,
                           __half* __restrict__ Th, __half* __restrict__ Tl) {
    __shared__ float t[64][65];
    int k0 = blockIdx.x * 64;
    int nt = blockIdx.y;                 // 0..47
    int mat = nt >> 4, h = nt & 15;
    const float* W = (mat == 0) ? Wq : (mat == 1) ? Wk : Wv;
    int tid = threadIdx.x;
    int ty = tid >> 4, tx = tid & 15;
    #pragma unroll
    for (int j = 0; j < 4; j++) {
        int ky = ty + 16 * j;
        float4 v = *(const float4*)(W + h * 65536 + (size_t)(k0 + ky) * 64 + tx * 4);
        t[ky][tx*4+0] = v.x; t[ky][tx*4+1] = v.y;
        t[ky][tx*4+2] = v.z; t[ky][tx*4+3] = v.w;
    }
    __syncthreads();
    int nr = tid >> 2, kc = (tid & 3) * 16;
    __half hh[16], hl[16];
    #pragma unroll
    for (int i = 0; i < 16; i++) {
        float w = t[kc + i][nr];
        __half hi = __float2half_rn(w);
        hh[i] = hi;
        hl[i] = __float2half_rn(w - __half2float(hi));
    }
    size_t n = (size_t)(mat * 1024 + h * 64 + nr);
    uint4* dh = (uint4*)(Th + n * CC + k0 + kc);
    uint4* dl = (uint4*)(Tl + n * CC + k0 + kc);
    dh[0] = *(uint4*)&hh[0]; dh[1] = *(uint4*)&hh[8];
    dl[0] = *(uint4*)&hl[0]; dl[1] = *(uint4*)&hl[8];
}

// W[K][N] f32 -> Wt[N][K] fp16, 64x64 tiles (validated R9: 2.1 TB/s)
__global__ void prep_t(const float* __restrict__ W, __half* __restrict__ Wt, int K, int N) {
    __shared__ float t[64][65];
    int n0 = blockIdx.x * 64, k0 = blockIdx.y * 64;
    int tid = threadIdx.x;
    int ty = tid >> 4, tx = tid & 15;
    #pragma unroll
    for (int j = 0; j < 4; j++) {
        float4 v = *(const float4*)(W + (size_t)(k0 + ty + 16*j) * N + n0 + tx*4);
        t[ty + 16*j][tx*4+0] = v.x; t[ty + 16*j][tx*4+1] = v.y;
        t[ty + 16*j][tx*4+2] = v.z; t[ty + 16*j][tx*4+3] = v.w;
    }
    __syncthreads();
    int nr = tid >> 2, kc = (tid & 3) * 16;
    __half h16[16];
    #pragma unroll
    for (int i = 0; i < 16; i++) h16[i] = __float2half_rn(t[kc + i][nr]);
    uint4* dst = (uint4*)(Wt + (size_t)(n0 + nr) * K + k0 + kc);
    dst[0] = *(uint4*)&h16[0];
    dst[1] = *(uint4*)&h16[8];
}

// ======================= LayerNorm: warp-per-row, no smem, no block sync =======================
template<int MODE>   // 2 = hi+lo, 1 = hi only
__global__ void ln_h(const float* __restrict__ X, const float* __restrict__ gam,
                     const float* __restrict__ bet,
                     __half* __restrict__ Yh, __half* __restrict__ Yl) {
    int warp = threadIdx.x >> 5, lane = threadIdx.x & 31;
    int row = blockIdx.x * 8 + warp;
    const float* xr = X + (size_t)row * CC;
    float4 v[8];
    float s = 0.f, ss = 0.f;
    #pragma unroll
    for (int i = 0; i < 8; i++) {
        v[i] = *(const float4*)(xr + i * 128 + lane * 4);
        s  += v[i].x + v[i].y + v[i].z + v[i].w;
        ss += v[i].x*v[i].x + v[i].y*v[i].y + v[i].z*v[i].z + v[i].w*v[i].w;
    }
    #pragma unroll
    for (int off = 16; off >= 1; off >>= 1) {
        s  += __shfl_xor_sync(0xffffffffu, s,  off);
        ss += __shfl_xor_sync(0xffffffffu, ss, off);
    }
    float mu  = s * (1.0f / CC);
    float var = ss * (1.0f / CC) - mu * mu;
    float rs  = rsqrtf(var + 1e-5f);
    #pragma unroll
    for (int i = 0; i < 8; i++) {
        int col = i * 128 + lane * 4;
        float4 gv = *(const float4*)(gam + col);
        float4 bv = *(const float4*)(bet + col);
        float y0 = (v[i].x - mu) * rs * gv.x + bv.x;
        float y1 = (v[i].y - mu) * rs * gv.y + bv.y;
        float y2 = (v[i].z - mu) * rs * gv.z + bv.z;
        float y3 = (v[i].w - mu) * rs * gv.w + bv.w;
        __half h0 = __float2half_rn(y0), h1 = __float2half_rn(y1);
        __half h2 = __float2half_rn(y2), h3 = __float2half_rn(y3);
        half2 a = __halves2half2(h0, h1);
        half2 b = __halves2half2(h2, h3);
        uint2 u; u.x = *(uint32_t*)&a; u.y = *(uint32_t*)&b;
        *(uint2*)(Yh + (size_t)row * CC + col) = u;
        if (MODE == 2) {
            half2 c = __halves2half2(__float2half_rn(y0 - __half2float(h0)),
                                     __float2half_rn(y1 - __half2float(h1)));
            half2 d = __halves2half2(__float2half_rn(y2 - __half2float(h2)),
                                     __float2half_rn(y3 - __half2float(h3)));
            uint2 w; w.x = *(uint32_t*)&c; w.y = *(uint32_t*)&d;
            *(uint2*)(Yl + (size_t)row * CC + col) = w;
        }
    }
}

// ============ fp16 GEMM: 128x128x32 tiles, 4-stage pipeline, occ 2 (R10 config) ============
#define GP 40                 // smem pitch in halves
#define GST 5120              // stage stride in halves (128*40)
#define NSTG 4
#define G_SMEM (NSTG*GST*2*2) // 81920 bytes
template<bool RELU, bool RESID, bool OUTH>
__global__ __launch_bounds__(256, 2) void gemm_h(
        const __half* __restrict__ A, const __half* __restrict__ Bt,
        const float* __restrict__ bias, const float* __restrict__ resid,
        void* __restrict__ Cv, int M, int N, int K) {
    extern __shared__ __half gsm[];
    __half* As = gsm;                 // [NSTG][GST]
    __half* Bs = gsm + NSTG*GST;
    int tid = threadIdx.x, l = tid & 31, warp = tid >> 5;
    int wy = warp >> 2, wx = warp & 3, lr = l >> 2, lc = l & 3;
    int m0 = blockIdx.y * 128, n0 = blockIdx.x * 128;
    int a_row = (l & 7) + ((l >> 3) & 1) * 8, a_k = (l >> 4) * 8;
    int b_row = (l & 7) + ((l >> 4) & 1) * 8, b_k = ((l >> 3) & 1) * 8;
    float acc[4][4][4];
    #pragma unroll
    for (int i = 0; i < 4; i++)
        #pragma unroll
        for (int j = 0; j < 4; j++)
            #pragma unroll
            for (int f = 0; f < 4; f++) acc[i][j][f] = 0.f;
    uint32_t sA = smem_u32(As), sB = smem_u32(Bs);
    int r1c = tid >> 2, g1c = tid & 3;
    int r2c = (tid + 256) >> 2;
    const int NT = K >> 5;
    auto loadT = [&](int kt, int st) {
        int k0 = kt * 32;
        uint32_t o1 = (uint32_t)((st*GST + r1c*GP + g1c*8) * 2);
        uint32_t o2 = (uint32_t)((st*GST + r2c*GP + g1c*8) * 2);
        cpa16(sA + o1, A + (size_t)(m0 + r1c) * K + k0 + g1c*8);
        cpa16(sA + o2, A + (size_t)(m0 + r2c) * K + k0 + g1c*8);
        cpa16(sB + o1, Bt + (size_t)(n0 + r1c) * K + k0 + g1c*8);
        cpa16(sB + o2, Bt + (size_t)(n0 + r2c) * K + k0 + g1c*8);
        cpcommit();
    };
    loadT(0, 0);
    loadT(1, 1);
    loadT(2, 2);
    int st = 0, ldst = 3;
    for (int kt = 0; kt < NT; kt++) {
        cpwait<NSTG-2>();
        __syncthreads();
        if (kt + 3 < NT) {
            loadT(kt + 3, ldst);
            if (++ldst == NSTG) ldst = 0;
        }
        #pragma unroll
        for (int ks = 0; ks < 2; ks++) {
            uint32_t af[4][4], bf[4][2];
            #pragma unroll
            for (int mi = 0; mi < 4; mi++) {
                uint32_t ad = sA + (uint32_t)((st*GST + (wy*64 + mi*16 + a_row)*GP
                                               + ks*16 + a_k) * 2);
                LDM_X4(af[mi][0], af[mi][1], af[mi][2], af[mi][3], ad);
            }
            #pragma unroll
            for (int nb = 0; nb < 2; nb++) {
                uint32_t ad = sB + (uint32_t)((st*GST + (wx*32 + nb*16 + b_row)*GP
                                               + ks*16 + b_k) * 2);
                uint32_t q0,q1,q2,q3;
                LDM_X4(q0,q1,q2,q3, ad);
                bf[nb*2][0]=q0; bf[nb*2][1]=q1; bf[nb*2+1][0]=q2; bf[nb*2+1][1]=q3;
            }
            #pragma unroll
            for (int mi = 0; mi < 4; mi++)
                #pragma unroll
                for (int nj = 0; nj < 4; nj++)
                    MMA_F16(acc[mi][nj], af[mi][0],af[mi][1],af[mi][2],af[mi][3],
                            bf[nj][0], bf[nj][1]);
        }
        if (++st == NSTG) st = 0;
    }
    #pragma unroll
    for (int mi = 0; mi < 4; mi++) {
        #pragma unroll
        for (int nj = 0; nj < 4; nj++) {
            int row = m0 + wy*64 + mi*16 + lr;
            int col = n0 + wx*32 + nj*8 + 2*lc;
            float b0 = bias[col], b1 = bias[col+1];
            float v0 = acc[mi][nj][0] + b0, v1 = acc[mi][nj][1] + b1;
            float v2 = acc[mi][nj][2] + b0, v3 = acc[mi][nj][3] + b1;
            if (RESID) {
                float2 q0 = *(const float2*)(resid + (size_t)row * N + col);
                float2 q1 = *(const float2*)(resid + (size_t)(row+8) * N + col);
                v0 += q0.x; v1 += q0.y; v2 += q1.x; v3 += q1.y;
            }
            if (RELU) {
                v0 = fmaxf(v0, 0.f); v1 = fmaxf(v1, 0.f);
                v2 = fmaxf(v2, 0.f); v3 = fmaxf(v3, 0.f);
            }
            if (OUTH) {
                __half* C = (__half*)Cv;
                *(half2*)(C + (size_t)row * N + col)     = __floats2half2_rn(v0, v1);
                *(half2*)(C + (size_t)(row+8) * N + col) = __floats2half2_rn(v2, v3);
            } else {
                float* C = (float*)Cv;
                *(float2*)(C + (size_t)row * N + col)     = make_float2(v0, v1);
                *(float2*)(C + (size_t)(row+8) * N + col) = make_float2(v2, v3);
            }
        }
    }
}

// ============ QKV GEMM: 3-term fp16 split, S=2 single-sync (R10 config) ============
#define QST 5120
#define QKV_SMEM (2*QST*4*2)   // 81920 B
__global__ __launch_bounds__(256) void gemm_qkv_h(
        const __half* __restrict__ Ah_, const __half* __restrict__ Al_,
        const __half* __restrict__ Bh_, const __half* __restrict__ Bl_,
        const float* __restrict__ bq, const float* __restrict__ bk_,
        const float* __restrict__ bv_,
        __half* __restrict__ qh, __half* __restrict__ ql,
        __half* __restrict__ kh, __half* __restrict__ kl,
        __half* __restrict__ vh) {
    extern __shared__ __half smq[];
    __half* Ah = smq;            // [2][5120]
    __half* Al = smq + 10240;
    __half* Bh = smq + 20480;
    __half* Bl = smq + 30720;
    const int K = CC;
    int tid = threadIdx.x, l = tid & 31, warp = tid >> 5;
    int wy = warp >> 2, wx = warp & 3, lr = l >> 2, lc = l & 3;
    int m0 = blockIdx.y * 128, n0 = blockIdx.x * 128;
    int a_row = (l & 7) + ((l >> 3) & 1) * 8, a_k = (l >> 4) * 8;
    int b_row = (l & 7) + ((l >> 4) & 1) * 8, b_k = ((l >> 3) & 1) * 8;
    float acc[4][4][4];
    #pragma unroll
    for (int i = 0; i < 4; i++)
        #pragma unroll
        for (int j = 0; j < 4; j++)
            #pragma unroll
            for (int f = 0; f < 4; f++) acc[i][j][f] = 0.f;
    uint32_t sAh = smem_u32(Ah), sAl = smem_u32(Al);
    uint32_t sBh = smem_u32(Bh), sBl = smem_u32(Bl);
    int r1c = tid >> 2, g1c = tid & 3;
    int r2c = (tid + 256) >> 2;
    const int NT = K >> 5;
    auto pf = [&](int kt, int st) {
        int k0 = kt * 32;
        uint32_t o1 = (uint32_t)((st*QST + r1c*GP + g1c*8) * 2);
        uint32_t o2 = (uint32_t)((st*QST + r2c*GP + g1c*8) * 2);
        cpa16(sAh + o1, Ah_ + (size_t)(m0 + r1c) * K + k0 + g1c*8);
        cpa16(sAh + o2, Ah_ + (size_t)(m0 + r2c) * K + k0 + g1c*8);
        cpa16(sBh + o1, Bh_ + (size_t)(n0 + r1c) * K + k0 + g1c*8);
        cpa16(sBh + o2, Bh_ + (size_t)(n0 + r2c) * K + k0 + g1c*8);
        cpa16(sAl + o1, Al_ + (size_t)(m0 + r1c) * K + k0 + g1c*8);
        cpa16(sAl + o2, Al_ + (size_t)(m0 + r2c) * K + k0 + g1c*8);
        cpa16(sBl + o1, Bl_ + (size_t)(n0 + r1c) * K + k0 + g1c*8);
        cpa16(sBl + o2, Bl_ + (size_t)(n0 + r2c) * K + k0 + g1c*8);
        cpcommit();
    };
    pf(0, 0);
    for (int kt = 0; kt < NT; kt++) {
        int st = kt & 1;
        cpwait<0>();
        __syncthreads();
        if (kt + 1 < NT) pf(kt + 1, st ^ 1);
        #pragma unroll
        for (int ks = 0; ks < 2; ks++) {
            uint32_t afh[4][4], afl[4][4];
            #pragma unroll
            for (int mi = 0; mi < 4; mi++) {
                uint32_t ao = (uint32_t)((st*QST + (wy*64 + mi*16 + a_row)*GP
                                          + ks*16 + a_k) * 2);
                LDM_X4(afh[mi][0], afh[mi][1], afh[mi][2], afh[mi][3], sAh + ao);
                LDM_X4(afl[mi][0], afl[mi][1], afl[mi][2], afl[mi][3], sAl + ao);
            }
            #pragma unroll
            for (int nb = 0; nb < 2; nb++) {
                uint32_t bo = (uint32_t)((st*QST + (wx*32 + nb*16 + b_row)*GP
                                          + ks*16 + b_k) * 2);
                uint32_t h0,h1,h2,h3, e0,e1,e2,e3;
                LDM_X4(h0,h1,h2,h3, sBh + bo);
                LDM_X4(e0,e1,e2,e3, sBl + bo);
                #pragma unroll
                for (int mi = 0; mi < 4; mi++) {
                    int nj = nb * 2;
                    MMA_F16(acc[mi][nj], afh[mi][0],afh[mi][1],afh[mi][2],afh[mi][3], e0,e1);
                    MMA_F16(acc[mi][nj], afl[mi][0],afl[mi][1],afl[mi][2],afl[mi][3], h0,h1);
                    MMA_F16(acc[mi][nj], afh[mi][0],afh[mi][1],afh[mi][2],afh[mi][3], h0,h1);
                    MMA_F16(acc[mi][nj+1], afh[mi][0],afh[mi][1],afh[mi][2],afh[mi][3], e2,e3);
                    MMA_F16(acc[mi][nj+1], afl[mi][0],afl[mi][1],afl[mi][2],afl[mi][3], h2,h3);
                    MMA_F16(acc[mi][nj+1], afh[mi][0],afh[mi][1],afh[mi][2],afh[mi][3], h2,h3);
                }
            }
        }
    }
    int mat = n0 >> 10, rem0 = n0 & 1023;
    const float* bias = (mat == 0) ? bq : (mat == 1) ? bk_ : bv_;
    // Q scaled by 8*log2(e): softmax runs in log2 domain
    float sc = (mat == 0) ? 8.0f * 1.4426950408889634f : 1.f;
    #pragma unroll
    for (int mi = 0; mi < 4; mi++) {
        #pragma unroll
        for (int nj = 0; nj < 4; nj++) {
            int row = m0 + wy*64 + mi*16 + lr;
            int col = rem0 + wx*32 + nj*8 + 2*lc;
            float b0 = bias[col], b1 = bias[col+1];
            float v0 = (acc[mi][nj][0] + b0) * sc, v1 = (acc[mi][nj][1] + b1) * sc;
            float v2 = (acc[mi][nj][2] + b0) * sc, v3 = (acc[mi][nj][3] + b1) * sc;
            size_t i0 = (size_t)row * CC + col, i1 = (size_t)(row+8) * CC + col;
            if (mat == 2) {
                *(half2*)(vh + i0) = __floats2half2_rn(v0, v1);
                *(half2*)(vh + i1) = __floats2half2_rn(v2, v3);
            } else {
                __half* oh = (mat == 0) ? qh : kh;
                __half* ol = (mat == 0) ? ql : kl;
                __half h0 = __float2half_rn(v0), h1 = __float2half_rn(v1);
                __half h2 = __float2half_rn(v2), h3 = __float2half_rn(v3);
                *(half2*)(oh + i0) = __halves2half2(h0, h1);
                *(half2*)(oh + i1) = __halves2half2(h2, h3);
                *(half2*)(ol + i0) = __halves2half2(
                    __float2half_rn(v0 - __half2float(h0)),
                    __float2half_rn(v1 - __half2float(h1)));
                *(half2*)(ol + i1) = __halves2half2(
                    __float2half_rn(v2 - __half2float(h2)),
                    __float2half_rn(v3 - __half2float(h3)));
            }
        }
    }
}

// ================= fp16 flash attention, BC=128, log2-domain softmax =================
#define PP 136
#define KSTG 9216
#define ATSMH (72704*2)
__global__ __launch_bounds__(256, 1) void attn_h(
        const __half* __restrict__ Qh_, const __half* __restrict__ Ql_,
        const __half* __restrict__ Kh_, const __half* __restrict__ Kl_,
        const __half* __restrict__ V_, __half* __restrict__ O_) {
    extern __shared__ __half sma[];
    __half* Ph = sma;
    __half* Kh = sma + 17408;
    __half* Kl = sma + 35840;
    __half* Vs = sma + 54272;
    uint32_t sPh = smem_u32(Ph), sKh = smem_u32(Kh), sKl = smem_u32(Kl), sVs = smem_u32(Vs);
    int tid = threadIdx.x, lane = tid & 31, warp = tid >> 5;
    int lr = lane >> 2, lc = lane & 3;
    int r0 = blockIdx.x * 128;
    int h  = blockIdx.y;
    int b  = blockIdx.z;
    size_t base = (size_t)b * TT * CC + h * DHH;

    int a_row = (lane & 7) + ((lane >> 3) & 1) * 8, a_k = (lane >> 4) * 8;
    int b_row = (lane & 7) + ((lane >> 4) & 1) * 8, b_k = ((lane >> 3) & 1) * 8;
    int v_row = (lane & 7) + ((lane >> 3) & 1) * 8, v_d = (lane >> 4) * 8;

    int c1r = tid >> 3, c1g = tid & 7;
    auto pfkv = [&](int t, int st) {
        int s0 = t * 128;
        #pragma unroll
        for (int i = 0; i < 4; i++) {
            int r = c1r + 32 * i;
            uint32_t o = (uint32_t)((st*KSTG + r*72 + c1g*8) * 2);
            size_t g = base + (size_t)(s0 + r) * CC + c1g*8;
            cpa16(sKh + o, Kh_ + g);
            cpa16(sKl + o, Kl_ + g);
            cpa16(sVs + o, V_ + g);
        }
        cpcommit();
    };
    pfkv(0, 0);

    uint32_t qfh[4][4], qfl[4][4];
    #pragma unroll
    for (int pass = 0; pass < 2; pass++) {
        const __half* src = pass ? Ql_ : Qh_;
        #pragma unroll
        for (int i = 0; i < 4; i++) {
            int c = tid + 256 * i;
            int row = c >> 3, cg = c & 7;
            *(uint4*)(Ph + row*PP + cg*8) =
                *(const uint4*)(src + base + (size_t)(r0 + row) * CC + cg*8);
        }
        __syncthreads();
        #pragma unroll
        for (int kt = 0; kt < 4; kt++) {
            uint32_t ad = sPh + (uint32_t)(((16*warp + a_row)*PP + kt*16 + a_k) * 2);
            if (pass) { LDM_X4(qfl[kt][0], qfl[kt][1], qfl[kt][2], qfl[kt][3], ad); }
            else      { LDM_X4(qfh[kt][0], qfh[kt][1], qfh[kt][2], qfh[kt][3], ad); }
        }
        __syncthreads();
    }

    float oacc[8][4];
    #pragma unroll
    for (int dj = 0; dj < 8; dj++)
        #pragma unroll
        for (int f = 0; f < 4; f++) oacc[dj][f] = 0.f;
    float m0 = -3e38f, m1 = -3e38f, l0 = 0.f, l1 = 0.f;

    const int NTL = TT / 128;   // 16
    for (int t = 0; t < NTL; t++) {
        int st = t & 1;
        cpwait<0>();
        __syncthreads();
        if (t + 1 < NTL) pfkv(t + 1, st ^ 1);

        float s[16][4];
        #pragma unroll
        for (int nj = 0; nj < 16; nj++)
            #pragma unroll
            for (int f = 0; f < 4; f++) s[nj][f] = 0.f;
        #pragma unroll
        for (int kt = 0; kt < 4; kt++) {
            #pragma unroll
            for (int nb = 0; nb < 8; nb++) {
                uint32_t off = (uint32_t)((st*KSTG + (nb*16 + b_row)*72
                                           + kt*16 + b_k) * 2);
                uint32_t h0,h1,h2,h3, e0,e1,e2,e3;
                LDM_X4(h0,h1,h2,h3, sKh + off);
                LDM_X4(e0,e1,e2,e3, sKl + off);
                int nj = nb * 2;
                MMA_F16(s[nj], qfh[kt][0],qfh[kt][1],qfh[kt][2],qfh[kt][3], e0,e1);
                MMA_F16(s[nj], qfl[kt][0],qfl[kt][1],qfl[kt][2],qfl[kt][3], h0,h1);
                MMA_F16(s[nj], qfh[kt][0],qfh[kt][1],qfh[kt][2],qfh[kt][3], h0,h1);
                MMA_F16(s[nj+1], qfh[kt][0],qfh[kt][1],qfh[kt][2],qfh[kt][3], e2,e3);
                MMA_F16(s[nj+1], qfl[kt][0],qfl[kt][1],qfl[kt][2],qfl[kt][3], h2,h3);
                MMA_F16(s[nj+1], qfh[kt][0],qfh[kt][1],qfh[kt][2],qfh[kt][3], h2,h3);
            }
        }
        // ---- online softmax (log2 domain: p = 2^(s-m)) ----
        float mt0 = -3e38f, mt1 = -3e38f;
        #pragma unroll
        for (int nj = 0; nj < 16; nj++) {
            mt0 = fmaxf(mt0, fmaxf(s[nj][0], s[nj][1]));
            mt1 = fmaxf(mt1, fmaxf(s[nj][2], s[nj][3]));
        }
        mt0 = fmaxf(mt0, __shfl_xor_sync(0xffffffffu, mt0, 1));
        mt0 = fmaxf(mt0, __shfl_xor_sync(0xffffffffu, mt0, 2));
        mt1 = fmaxf(mt1, __shfl_xor_sync(0xffffffffu, mt1, 1));
        mt1 = fmaxf(mt1, __shfl_xor_sync(0xffffffffu, mt1, 2));
        float mn0 = fmaxf(m0, mt0), mn1 = fmaxf(m1, mt1);
        float al0 = ex2f(m0 - mn0), al1 = ex2f(m1 - mn1);
        float ps0 = 0.f, ps1 = 0.f;
        int pr0 = (16*warp + lr) * PP, pr1 = (16*warp + 8 + lr) * PP;
        #pragma unroll
        for (int nj = 0; nj < 16; nj++) {
            float p0 = ex2f(s[nj][0] - mn0);
            float p1 = ex2f(s[nj][1] - mn0);
            float p2 = ex2f(s[nj][2] - mn1);
            float p3 = ex2f(s[nj][3] - mn1);
            ps0 += p0 + p1; ps1 += p2 + p3;
            *(half2*)(Ph + pr0 + nj*8 + 2*lc) = __floats2half2_rn(p0, p1);
            *(half2*)(Ph + pr1 + nj*8 + 2*lc) = __floats2half2_rn(p2, p3);
        }
        ps0 += __shfl_xor_sync(0xffffffffu, ps0, 1);
        ps0 += __shfl_xor_sync(0xffffffffu, ps0, 2);
        ps1 += __shfl_xor_sync(0xffffffffu, ps1, 1);
        ps1 += __shfl_xor_sync(0xffffffffu, ps1, 2);
        l0 = l0 * al0 + ps0;
        l1 = l1 * al1 + ps1;
        m0 = mn0; m1 = mn1;
        #pragma unroll
        for (int dj = 0; dj < 8; dj++) {
            oacc[dj][0] *= al0; oacc[dj][1] *= al0;
            oacc[dj][2] *= al1; oacc[dj][3] *= al1;
        }
        __syncwarp();
        #pragma unroll
        for (int kt = 0; kt < 8; kt++) {
            uint32_t pa0,pa1,pa2,pa3;
            LDM_X4(pa0,pa1,pa2,pa3,
                   sPh + (uint32_t)(((16*warp + a_row)*PP + kt*16 + a_k) * 2));
            #pragma unroll
            for (int dp = 0; dp < 4; dp++) {
                uint32_t v0,v1,v2,v3;
                uint32_t ad = sVs + (uint32_t)((st*KSTG + (kt*16 + v_row)*72
                                                + dp*16 + v_d) * 2);
                LDM_X4T(v0,v1,v2,v3, ad);
                MMA_F16(oacc[dp*2],   pa0,pa1,pa2,pa3, v0,v1);
                MMA_F16(oacc[dp*2+1], pa0,pa1,pa2,pa3, v2,v3);
            }
        }
    }
    float inv0 = 1.f / l0, inv1 = 1.f / l1;
    int row0 = r0 + 16*warp + lr, row1 = row0 + 8;
    #pragma unroll
    for (int dj = 0; dj < 8; dj++) {
        int col = dj*8 + 2*lc;
        *(half2*)(O_ + base + (size_t)row0 * CC + col) =
            __floats2half2_rn(oacc[dj][0]*inv0, oacc[dj][1]*inv0);
        *(half2*)(O_ + base + (size_t)row1 * CC + col) =
            __floats2half2_rn(oacc[dj][2]*inv1, oacc[dj][3]*inv1);
    }
}

// ========================= launch =========================
extern "C" void kernel_launch(void* const* d_in, const int* in_sizes, int n_in,
                              void* d_out, int out_size) {
    const float* x     = (const float*)d_in[0];
    const float* Wq    = (const float*)d_in[1];
    const float* bq    = (const float*)d_in[2];
    const float* Wk    = (const float*)d_in[3];
    const float* bk    = (const float*)d_in[4];
    const float* Wv    = (const float*)d_in[5];
    const float* bv    = (const float*)d_in[6];
    const float* Wo    = (const float*)d_in[7];
    const float* bo    = (const float*)d_in[8];
    const float* ln1g  = (const float*)d_in[9];
    const float* ln1b  = (const float*)d_in[10];
    const float* ln2g  = (const float*)d_in[11];
    const float* ln2b  = (const float*)d_in[12];
    const float* W1    = (const float*)d_in[13];
    const float* b1    = (const float*)d_in[14];
    const float* W2    = (const float*)d_in[15];
    const float* b2    = (const float*)d_in[16];
    float* out = (float*)d_out;

    __half *xnh,*xnl,*qh,*ql,*kh,*kl,*vh,*oh,*x2h,*ffh,*wqh,*wql,*wot,*w1t,*w2t;
    float *x1;
    cudaGetSymbolAddress((void**)&xnh, g_xnh);
    cudaGetSymbolAddress((void**)&xnl, g_xnl);
    cudaGetSymbolAddress((void**)&qh,  g_qhh);
    cudaGetSymbolAddress((void**)&ql,  g_qll);
    cudaGetSymbolAddress((void**)&kh,  g_khh);
    cudaGetSymbolAddress((void**)&kl,  g_kll);
    cudaGetSymbolAddress((void**)&vh,  g_vhh);
    cudaGetSymbolAddress((void**)&oh,  g_ohh);
    cudaGetSymbolAddress((void**)&x2h, g_x2h);
    cudaGetSymbolAddress((void**)&ffh, g_ffh);
    cudaGetSymbolAddress((void**)&x1,  g_x1);
    cudaGetSymbolAddress((void**)&wqh, g_wqh);
    cudaGetSymbolAddress((void**)&wql, g_wql);
    cudaGetSymbolAddress((void**)&wot, g_wot);
    cudaGetSymbolAddress((void**)&w1t, g_w1t);
    cudaGetSymbolAddress((void**)&w2t, g_w2t);

    cudaFuncSetAttribute(gemm_qkv_h, cudaFuncAttributeMaxDynamicSharedMemorySize, QKV_SMEM);
    cudaFuncSetAttribute(attn_h, cudaFuncAttributeMaxDynamicSharedMemorySize, ATSMH);
    cudaFuncSetAttribute(gemm_h<false,true,false>,
                         cudaFuncAttributeMaxDynamicSharedMemorySize, G_SMEM);
    cudaFuncSetAttribute(gemm_h<true,false,true>,
                         cudaFuncAttributeMaxDynamicSharedMemorySize, G_SMEM);

    // weight prep
    prep_qkv_h<<<dim3(16, 48), 256>>>(Wq, Wk, Wv, wqh, wql);
    prep_t<<<dim3(16, 16), 256>>>(Wo, wot, 1024, 1024);
    prep_t<<<dim3(64, 16), 256>>>(W1, w1t, 1024, 4096);
    prep_t<<<dim3(16, 64), 256>>>(W2, w2t, 4096, 1024);

    // 1) LN1 (hi+lo fp16), warp-per-row
    ln_h<2><<<MM/8, 256>>>(x, ln1g, ln1b, xnh, xnl);
    // 2) QKV (3-term fp16, S=2)
    gemm_qkv_h<<<dim3(24, 64), 256, QKV_SMEM>>>(xnh, xnl, wqh, wql,
                                                bq, bk, bv, qh, ql, kh, kl, vh);
    // 3) attention (fp16 TC flash, BC=128, log2 softmax)
    attn_h<<<dim3(TT/128, HH, BB), 256, ATSMH>>>(qh, ql, kh, kl, vh, oh);
    // 4) out proj + residual -> x1 (fp32)
    gemm_h<false, true, false><<<dim3(8, 64), 256, G_SMEM>>>(oh, wot, bo, x, (void*)x1, MM, CC, CC);
    // 5) LN2 (fp16 hi), warp-per-row
    ln_h<1><<<MM/8, 256>>>(x1, ln2g, ln2b, x2h, nullptr);
    // 6) FFN1 (relu, fp16 out)
    gemm_h<true, false, true><<<dim3(32, 64), 256, G_SMEM>>>(x2h, w1t, b1, nullptr, (void*)ffh, MM, DFF, CC);
    // 7) FFN2 + residual -> out (fp32)
    gemm_h<false, true, false><<<dim3(8, 64), 256, G_SMEM>>>(ffh, w2t, b2, x1, (void*)out, MM, CC, DFF);
}

// round 14
// speedup vs baseline: 1.0968x; 1.0186x over previous
#include <cuda_runtime.h>
#include <cuda_fp16.h>
#include <math.h>
#include <stdint.h>

#define BB 4
#define TT 2048
#define CC 1024
#define HH 16
#define DHH 64
#define DFF 4096
#define MM (BB*TT)   /* 8192 */

// -------- scratch (device globals; no allocation) --------
__device__ __half g_xnh[(size_t)MM*CC];
__device__ __half g_xnl[(size_t)MM*CC];
__device__ __half g_qhh[(size_t)MM*CC];
__device__ __half g_qll[(size_t)MM*CC];
__device__ __half g_khh[(size_t)MM*CC];
__device__ __half g_kll[(size_t)MM*CC];
__device__ __half g_vhh[(size_t)MM*CC];
__device__ __half g_ohh[(size_t)MM*CC];
__device__ __half g_x2h[(size_t)MM*CC];
__device__ __half g_ffh[(size_t)MM*DFF];
__device__ float  g_x1 [(size_t)MM*CC];
__device__ __half g_wqh[(size_t)CC*3072];
__device__ __half g_wql[(size_t)CC*3072];
__device__ __half g_wot[(size_t)CC*CC];
__device__ __half g_w1t[(size_t)CC*DFF];
__device__ __half g_w2t[(size_t)DFF*CC];

// ======================= helpers =======================
__device__ __forceinline__ uint32_t smem_u32(const void* p) {
    return (uint32_t)__cvta_generic_to_shared(p);
}
__device__ __forceinline__ float ex2f(float x) {
    float r;
    asm("ex2.approx.f32 %0, %1;" : "=f"(r) : "f"(x));
    return r;
}
#define LDM_X4(r0,r1,r2,r3, addr) \
    asm volatile("ldmatrix.sync.aligned.m8n8.x4.shared.b16 {%0,%1,%2,%3},[%4];" \
        : "=r"(r0),"=r"(r1),"=r"(r2),"=r"(r3) : "r"(addr))
#define LDM_X4T(r0,r1,r2,r3, addr) \
    asm volatile("ldmatrix.sync.aligned.m8n8.x4.trans.shared.b16 {%0,%1,%2,%3},[%4];" \
        : "=r"(r0),"=r"(r1),"=r"(r2),"=r"(r3) : "r"(addr))
#define MMA_F16(d, a0,a1,a2,a3, b0,b1) \
    asm volatile("mma.sync.aligned.m16n8k16.row.col.f32.f16.f16.f32 " \
        "{%0,%1,%2,%3},{%4,%5,%6,%7},{%8,%9},{%0,%1,%2,%3};" \
        : "+f"(d[0]),"+f"(d[1]),"+f"(d[2]),"+f"(d[3]) \
        : "r"(a0),"r"(a1),"r"(a2),"r"(a3),"r"(b0),"r"(b1))

__device__ __forceinline__ void cpa16(uint32_t dst, const void* src) {
    asm volatile("cp.async.cg.shared.global [%0], [%1], 16;\n" :: "r"(dst), "l"(src));
}
__device__ __forceinline__ void cpcommit() { asm volatile("cp.async.commit_group;\n" ::); }
template<int N> __device__ __forceinline__ void cpwait() {
    asm volatile("cp.async.wait_group %0;\n" :: "n"(N));
}

// ======================= prep kernels =======================
// Wqkv [H][C][DH] -> Th/Tl [n=3072][k=1024], vectorized 64x64 transpose
__global__ void prep_qkv_h(const float* __restrict__ Wq, const float* __restrict__ Wk,
                           const float* __restrict__ Wv,
                           __half* __restrict__ Th, __half* __restrict__ Tl) {
    __shared__ float t[64][65];
    int k0 = blockIdx.x * 64;
    int nt = blockIdx.y;                 // 0..47
    int mat = nt >> 4, h = nt & 15;
    const float* W = (mat == 0) ? Wq : (mat == 1) ? Wk : Wv;
    int tid = threadIdx.x;
    int ty = tid >> 4, tx = tid & 15;
    #pragma unroll
    for (int j = 0; j < 4; j++) {
        int ky = ty + 16 * j;
        float4 v = *(const float4*)(W + h * 65536 + (size_t)(k0 + ky) * 64 + tx * 4);
        t[ky][tx*4+0] = v.x; t[ky][tx*4+1] = v.y;
        t[ky][tx*4+2] = v.z; t[ky][tx*4+3] = v.w;
    }
    __syncthreads();
    int nr = tid >> 2, kc = (tid & 3) * 16;
    __half hh[16], hl[16];
    #pragma unroll
    for (int i = 0; i < 16; i++) {
        float w = t[kc + i][nr];
        __half hi = __float2half_rn(w);
        hh[i] = hi;
        hl[i] = __float2half_rn(w - __half2float(hi));
    }
    size_t n = (size_t)(mat * 1024 + h * 64 + nr);
    uint4* dh = (uint4*)(Th + n * CC + k0 + kc);
    uint4* dl = (uint4*)(Tl + n * CC + k0 + kc);
    dh[0] = *(uint4*)&hh[0]; dh[1] = *(uint4*)&hh[8];
    dl[0] = *(uint4*)&hl[0]; dl[1] = *(uint4*)&hl[8];
}

// W[K][N] f32 -> Wt[N][K] fp16, 64x64 tiles (validated R9: 2.1 TB/s)
__global__ void prep_t(const float* __restrict__ W, __half* __restrict__ Wt, int K, int N) {
    __shared__ float t[64][65];
    int n0 = blockIdx.x * 64, k0 = blockIdx.y * 64;
    int tid = threadIdx.x;
    int ty = tid >> 4, tx = tid & 15;
    #pragma unroll
    for (int j = 0; j < 4; j++) {
        float4 v = *(const float4*)(W + (size_t)(k0 + ty + 16*j) * N + n0 + tx*4);
        t[ty + 16*j][tx*4+0] = v.x; t[ty + 16*j][tx*4+1] = v.y;
        t[ty + 16*j][tx*4+2] = v.z; t[ty + 16*j][tx*4+3] = v.w;
    }
    __syncthreads();
    int nr = tid >> 2, kc = (tid & 3) * 16;
    __half h16[16];
    #pragma unroll
    for (int i = 0; i < 16; i++) h16[i] = __float2half_rn(t[kc + i][nr]);
    uint4* dst = (uint4*)(Wt + (size_t)(n0 + nr) * K + k0 + kc);
    dst[0] = *(uint4*)&h16[0];
    dst[1] = *(uint4*)&h16[8];
}

// ======================= LayerNorm: warp-per-row, no smem, no block sync =======================
template<int MODE>   // 2 = hi+lo, 1 = hi only
__global__ void ln_h(const float* __restrict__ X, const float* __restrict__ gam,
                     const float* __restrict__ bet,
                     __half* __restrict__ Yh, __half* __restrict__ Yl) {
    int warp = threadIdx.x >> 5, lane = threadIdx.x & 31;
    int row = blockIdx.x * 8 + warp;
    const float* xr = X + (size_t)row * CC;
    float4 v[8];
    float s = 0.f, ss = 0.f;
    #pragma unroll
    for (int i = 0; i < 8; i++) {
        v[i] = *(const float4*)(xr + i * 128 + lane * 4);
        s  += v[i].x + v[i].y + v[i].z + v[i].w;
        ss += v[i].x*v[i].x + v[i].y*v[i].y + v[i].z*v[i].z + v[i].w*v[i].w;
    }
    #pragma unroll
    for (int off = 16; off >= 1; off >>= 1) {
        s  += __shfl_xor_sync(0xffffffffu, s,  off);
        ss += __shfl_xor_sync(0xffffffffu, ss, off);
    }
    float mu  = s * (1.0f / CC);
    float var = ss * (1.0f / CC) - mu * mu;
    float rs  = rsqrtf(var + 1e-5f);
    #pragma unroll
    for (int i = 0; i < 8; i++) {
        int col = i * 128 + lane * 4;
        float4 gv = *(const float4*)(gam + col);
        float4 bv = *(const float4*)(bet + col);
        float y0 = (v[i].x - mu) * rs * gv.x + bv.x;
        float y1 = (v[i].y - mu) * rs * gv.y + bv.y;
        float y2 = (v[i].z - mu) * rs * gv.z + bv.z;
        float y3 = (v[i].w - mu) * rs * gv.w + bv.w;
        __half h0 = __float2half_rn(y0), h1 = __float2half_rn(y1);
        __half h2 = __float2half_rn(y2), h3 = __float2half_rn(y3);
        half2 a = __halves2half2(h0, h1);
        half2 b = __halves2half2(h2, h3);
        uint2 u; u.x = *(uint32_t*)&a; u.y = *(uint32_t*)&b;
        *(uint2*)(Yh + (size_t)row * CC + col) = u;
        if (MODE == 2) {
            half2 c = __halves2half2(__float2half_rn(y0 - __half2float(h0)),
                                     __float2half_rn(y1 - __half2float(h1)));
            half2 d = __halves2half2(__float2half_rn(y2 - __half2float(h2)),
                                     __float2half_rn(y3 - __half2float(h3)));
            uint2 w; w.x = *(uint32_t*)&c; w.y = *(uint32_t*)&d;
            *(uint2*)(Yl + (size_t)row * CC + col) = w;
        }
    }
}

// ============ fp16 GEMM: 128x128x32 tiles, 4-stage pipeline, occ 2 (R10 config) ============
#define GP 40                 // smem pitch in halves
#define GST 5120              // stage stride in halves (128*40)
#define NSTG 4
#define G_SMEM (NSTG*GST*2*2) // 81920 bytes
template<bool RELU, bool RESID, bool OUTH>
__global__ __launch_bounds__(256, 2) void gemm_h(
        const __half* __restrict__ A, const __half* __restrict__ Bt,
        const float* __restrict__ bias, const float* __restrict__ resid,
        void* __restrict__ Cv, int M, int N, int K) {
    extern __shared__ __half gsm[];
    __half* As = gsm;                 // [NSTG][GST]
    __half* Bs = gsm + NSTG*GST;
    int tid = threadIdx.x, l = tid & 31, warp = tid >> 5;
    int wy = warp >> 2, wx = warp & 3, lr = l >> 2, lc = l & 3;
    int m0 = blockIdx.y * 128, n0 = blockIdx.x * 128;
    int a_row = (l & 7) + ((l >> 3) & 1) * 8, a_k = (l >> 4) * 8;
    int b_row = (l & 7) + ((l >> 4) & 1) * 8, b_k = ((l >> 3) & 1) * 8;
    float acc[4][4][4];
    #pragma unroll
    for (int i = 0; i < 4; i++)
        #pragma unroll
        for (int j = 0; j < 4; j++)
            #pragma unroll
            for (int f = 0; f < 4; f++) acc[i][j][f] = 0.f;
    uint32_t sA = smem_u32(As), sB = smem_u32(Bs);
    int r1c = tid >> 2, g1c = tid & 3;
    int r2c = (tid + 256) >> 2;
    const int NT = K >> 5;
    auto loadT = [&](int kt, int st) {
        int k0 = kt * 32;
        uint32_t o1 = (uint32_t)((st*GST + r1c*GP + g1c*8) * 2);
        uint32_t o2 = (uint32_t)((st*GST + r2c*GP + g1c*8) * 2);
        cpa16(sA + o1, A + (size_t)(m0 + r1c) * K + k0 + g1c*8);
        cpa16(sA + o2, A + (size_t)(m0 + r2c) * K + k0 + g1c*8);
        cpa16(sB + o1, Bt + (size_t)(n0 + r1c) * K + k0 + g1c*8);
        cpa16(sB + o2, Bt + (size_t)(n0 + r2c) * K + k0 + g1c*8);
        cpcommit();
    };
    loadT(0, 0);
    loadT(1, 1);
    loadT(2, 2);
    int st = 0, ldst = 3;
    for (int kt = 0; kt < NT; kt++) {
        cpwait<NSTG-2>();
        __syncthreads();
        if (kt + 3 < NT) {
            loadT(kt + 3, ldst);
            if (++ldst == NSTG) ldst = 0;
        }
        #pragma unroll
        for (int ks = 0; ks < 2; ks++) {
            uint32_t af[4][4], bf[4][2];
            #pragma unroll
            for (int mi = 0; mi < 4; mi++) {
                uint32_t ad = sA + (uint32_t)((st*GST + (wy*64 + mi*16 + a_row)*GP
                                               + ks*16 + a_k) * 2);
                LDM_X4(af[mi][0], af[mi][1], af[mi][2], af[mi][3], ad);
            }
            #pragma unroll
            for (int nb = 0; nb < 2; nb++) {
                uint32_t ad = sB + (uint32_t)((st*GST + (wx*32 + nb*16 + b_row)*GP
                                               + ks*16 + b_k) * 2);
                uint32_t q0,q1,q2,q3;
                LDM_X4(q0,q1,q2,q3, ad);
                bf[nb*2][0]=q0; bf[nb*2][1]=q1; bf[nb*2+1][0]=q2; bf[nb*2+1][1]=q3;
            }
            #pragma unroll
            for (int mi = 0; mi < 4; mi++)
                #pragma unroll
                for (int nj = 0; nj < 4; nj++)
                    MMA_F16(acc[mi][nj], af[mi][0],af[mi][1],af[mi][2],af[mi][3],
                            bf[nj][0], bf[nj][1]);
        }
        if (++st == NSTG) st = 0;
    }
    #pragma unroll
    for (int mi = 0; mi < 4; mi++) {
        #pragma unroll
        for (int nj = 0; nj < 4; nj++) {
            int row = m0 + wy*64 + mi*16 + lr;
            int col = n0 + wx*32 + nj*8 + 2*lc;
            float b0 = bias[col], b1 = bias[col+1];
            float v0 = acc[mi][nj][0] + b0, v1 = acc[mi][nj][1] + b1;
            float v2 = acc[mi][nj][2] + b0, v3 = acc[mi][nj][3] + b1;
            if (RESID) {
                float2 q0 = *(const float2*)(resid + (size_t)row * N + col);
                float2 q1 = *(const float2*)(resid + (size_t)(row+8) * N + col);
                v0 += q0.x; v1 += q0.y; v2 += q1.x; v3 += q1.y;
            }
            if (RELU) {
                v0 = fmaxf(v0, 0.f); v1 = fmaxf(v1, 0.f);
                v2 = fmaxf(v2, 0.f); v3 = fmaxf(v3, 0.f);
            }
            if (OUTH) {
                __half* C = (__half*)Cv;
                *(half2*)(C + (size_t)row * N + col)     = __floats2half2_rn(v0, v1);
                *(half2*)(C + (size_t)(row+8) * N + col) = __floats2half2_rn(v2, v3);
            } else {
                float* C = (float*)Cv;
                *(float2*)(C + (size_t)row * N + col)     = make_float2(v0, v1);
                *(float2*)(C + (size_t)(row+8) * N + col) = make_float2(v2, v3);
            }
        }
    }
}

// ============ QKV GEMM: 3-term fp16 for Q/K tiles, 1-term for V tiles ============
#define QST 5120
#define QKV_SMEM (2*QST*4*2)   // 81920 B
__global__ __launch_bounds__(256) void gemm_qkv_h(
        const __half* __restrict__ Ah_, const __half* __restrict__ Al_,
        const __half* __restrict__ Bh_, const __half* __restrict__ Bl_,
        const float* __restrict__ bq, const float* __restrict__ bk_,
        const float* __restrict__ bv_,
        __half* __restrict__ qh, __half* __restrict__ ql,
        __half* __restrict__ kh, __half* __restrict__ kl,
        __half* __restrict__ vh) {
    extern __shared__ __half smq[];
    __half* Ah = smq;            // [2][5120]
    __half* Al = smq + 10240;
    __half* Bh = smq + 20480;
    __half* Bl = smq + 30720;
    const int K = CC;
    int tid = threadIdx.x, l = tid & 31, warp = tid >> 5;
    int wy = warp >> 2, wx = warp & 3, lr = l >> 2, lc = l & 3;
    int m0 = blockIdx.y * 128, n0 = blockIdx.x * 128;
    int mat = n0 >> 10;
    const bool three = (mat < 2);   // V tiles: 1-term fp16 suffices (rounded at epilogue)
    int a_row = (l & 7) + ((l >> 3) & 1) * 8, a_k = (l >> 4) * 8;
    int b_row = (l & 7) + ((l >> 4) & 1) * 8, b_k = ((l >> 3) & 1) * 8;
    float acc[4][4][4];
    #pragma unroll
    for (int i = 0; i < 4; i++)
        #pragma unroll
        for (int j = 0; j < 4; j++)
            #pragma unroll
            for (int f = 0; f < 4; f++) acc[i][j][f] = 0.f;
    uint32_t sAh = smem_u32(Ah), sAl = smem_u32(Al);
    uint32_t sBh = smem_u32(Bh), sBl = smem_u32(Bl);
    int r1c = tid >> 2, g1c = tid & 3;
    int r2c = (tid + 256) >> 2;
    const int NT = K >> 5;
    auto pf = [&](int kt, int st) {
        int k0 = kt * 32;
        uint32_t o1 = (uint32_t)((st*QST + r1c*GP + g1c*8) * 2);
        uint32_t o2 = (uint32_t)((st*QST + r2c*GP + g1c*8) * 2);
        cpa16(sAh + o1, Ah_ + (size_t)(m0 + r1c) * K + k0 + g1c*8);
        cpa16(sAh + o2, Ah_ + (size_t)(m0 + r2c) * K + k0 + g1c*8);
        cpa16(sBh + o1, Bh_ + (size_t)(n0 + r1c) * K + k0 + g1c*8);
        cpa16(sBh + o2, Bh_ + (size_t)(n0 + r2c) * K + k0 + g1c*8);
        if (three) {
            cpa16(sAl + o1, Al_ + (size_t)(m0 + r1c) * K + k0 + g1c*8);
            cpa16(sAl + o2, Al_ + (size_t)(m0 + r2c) * K + k0 + g1c*8);
            cpa16(sBl + o1, Bl_ + (size_t)(n0 + r1c) * K + k0 + g1c*8);
            cpa16(sBl + o2, Bl_ + (size_t)(n0 + r2c) * K + k0 + g1c*8);
        }
        cpcommit();
    };
    pf(0, 0);
    for (int kt = 0; kt < NT; kt++) {
        int st = kt & 1;
        cpwait<0>();
        __syncthreads();
        if (kt + 1 < NT) pf(kt + 1, st ^ 1);
        #pragma unroll
        for (int ks = 0; ks < 2; ks++) {
            uint32_t afh[4][4], afl[4][4];
            #pragma unroll
            for (int mi = 0; mi < 4; mi++) {
                uint32_t ao = (uint32_t)((st*QST + (wy*64 + mi*16 + a_row)*GP
                                          + ks*16 + a_k) * 2);
                LDM_X4(afh[mi][0], afh[mi][1], afh[mi][2], afh[mi][3], sAh + ao);
                if (three)
                    LDM_X4(afl[mi][0], afl[mi][1], afl[mi][2], afl[mi][3], sAl + ao);
            }
            #pragma unroll
            for (int nb = 0; nb < 2; nb++) {
                uint32_t bo = (uint32_t)((st*QST + (wx*32 + nb*16 + b_row)*GP
                                          + ks*16 + b_k) * 2);
                uint32_t h0,h1,h2,h3, e0,e1,e2,e3;
                LDM_X4(h0,h1,h2,h3, sBh + bo);
                if (three) { LDM_X4(e0,e1,e2,e3, sBl + bo); }
                #pragma unroll
                for (int mi = 0; mi < 4; mi++) {
                    int nj = nb * 2;
                    if (three) {
                        MMA_F16(acc[mi][nj], afh[mi][0],afh[mi][1],afh[mi][2],afh[mi][3], e0,e1);
                        MMA_F16(acc[mi][nj], afl[mi][0],afl[mi][1],afl[mi][2],afl[mi][3], h0,h1);
                        MMA_F16(acc[mi][nj+1], afh[mi][0],afh[mi][1],afh[mi][2],afh[mi][3], e2,e3);
                        MMA_F16(acc[mi][nj+1], afl[mi][0],afl[mi][1],afl[mi][2],afl[mi][3], h2,h3);
                    }
                    MMA_F16(acc[mi][nj], afh[mi][0],afh[mi][1],afh[mi][2],afh[mi][3], h0,h1);
                    MMA_F16(acc[mi][nj+1], afh[mi][0],afh[mi][1],afh[mi][2],afh[mi][3], h2,h3);
                }
            }
        }
    }
    int rem0 = n0 & 1023;
    const float* bias = (mat == 0) ? bq : (mat == 1) ? bk_ : bv_;
    // Q scaled by 8*log2(e): softmax runs in log2 domain
    float sc = (mat == 0) ? 8.0f * 1.4426950408889634f : 1.f;
    #pragma unroll
    for (int mi = 0; mi < 4; mi++) {
        #pragma unroll
        for (int nj = 0; nj < 4; nj++) {
            int row = m0 + wy*64 + mi*16 + lr;
            int col = rem0 + wx*32 + nj*8 + 2*lc;
            float b0 = bias[col], b1 = bias[col+1];
            float v0 = (acc[mi][nj][0] + b0) * sc, v1 = (acc[mi][nj][1] + b1) * sc;
            float v2 = (acc[mi][nj][2] + b0) * sc, v3 = (acc[mi][nj][3] + b1) * sc;
            size_t i0 = (size_t)row * CC + col, i1 = (size_t)(row+8) * CC + col;
            if (mat == 2) {
                *(half2*)(vh + i0) = __floats2half2_rn(v0, v1);
                *(half2*)(vh + i1) = __floats2half2_rn(v2, v3);
            } else {
                __half* oh = (mat == 0) ? qh : kh;
                __half* ol = (mat == 0) ? ql : kl;
                __half h0 = __float2half_rn(v0), h1 = __float2half_rn(v1);
                __half h2 = __float2half_rn(v2), h3 = __float2half_rn(v3);
                *(half2*)(oh + i0) = __halves2half2(h0, h1);
                *(half2*)(oh + i1) = __halves2half2(h2, h3);
                *(half2*)(ol + i0) = __halves2half2(
                    __float2half_rn(v0 - __half2float(h0)),
                    __float2half_rn(v1 - __half2float(h1)));
                *(half2*)(ol + i1) = __halves2half2(
                    __float2half_rn(v2 - __half2float(h2)),
                    __float2half_rn(v3 - __half2float(h3)));
            }
        }
    }
}

// ================= fp16 flash attention, BC=128, log2-domain softmax =================
#define PP 136
#define KSTG 9216
#define ATSMH (72704*2)
__global__ __launch_bounds__(256, 1) void attn_h(
        const __half* __restrict__ Qh_, const __half* __restrict__ Ql_,
        const __half* __restrict__ Kh_, const __half* __restrict__ Kl_,
        const __half* __restrict__ V_, __half* __restrict__ O_) {
    extern __shared__ __half sma[];
    __half* Ph = sma;
    __half* Kh = sma + 17408;
    __half* Kl = sma + 35840;
    __half* Vs = sma + 54272;
    uint32_t sPh = smem_u32(Ph), sKh = smem_u32(Kh), sKl = smem_u32(Kl), sVs = smem_u32(Vs);
    int tid = threadIdx.x, lane = tid & 31, warp = tid >> 5;
    int lr = lane >> 2, lc = lane & 3;
    int r0 = blockIdx.x * 128;
    int h  = blockIdx.y;
    int b  = blockIdx.z;
    size_t base = (size_t)b * TT * CC + h * DHH;

    int a_row = (lane & 7) + ((lane >> 3) & 1) * 8, a_k = (lane >> 4) * 8;
    int b_row = (lane & 7) + ((lane >> 4) & 1) * 8, b_k = ((lane >> 3) & 1) * 8;
    int v_row = (lane & 7) + ((lane >> 3) & 1) * 8, v_d = (lane >> 4) * 8;

    int c1r = tid >> 3, c1g = tid & 7;
    auto pfkv = [&](int t, int st) {
        int s0 = t * 128;
        #pragma unroll
        for (int i = 0; i < 4; i++) {
            int r = c1r + 32 * i;
            uint32_t o = (uint32_t)((st*KSTG + r*72 + c1g*8) * 2);
            size_t g = base + (size_t)(s0 + r) * CC + c1g*8;
            cpa16(sKh + o, Kh_ + g);
            cpa16(sKl + o, Kl_ + g);
            cpa16(sVs + o, V_ + g);
        }
        cpcommit();
    };
    pfkv(0, 0);

    uint32_t qfh[4][4], qfl[4][4];
    #pragma unroll
    for (int pass = 0; pass < 2; pass++) {
        const __half* src = pass ? Ql_ : Qh_;
        #pragma unroll
        for (int i = 0; i < 4; i++) {
            int c = tid + 256 * i;
            int row = c >> 3, cg = c & 7;
            *(uint4*)(Ph + row*PP + cg*8) =
                *(const uint4*)(src + base + (size_t)(r0 + row) * CC + cg*8);
        }
        __syncthreads();
        #pragma unroll
        for (int kt = 0; kt < 4; kt++) {
            uint32_t ad = sPh + (uint32_t)(((16*warp + a_row)*PP + kt*16 + a_k) * 2);
            if (pass) { LDM_X4(qfl[kt][0], qfl[kt][1], qfl[kt][2], qfl[kt][3], ad); }
            else      { LDM_X4(qfh[kt][0], qfh[kt][1], qfh[kt][2], qfh[kt][3], ad); }
        }
        __syncthreads();
    }

    float oacc[8][4];
    #pragma unroll
    for (int dj = 0; dj < 8; dj++)
        #pragma unroll
        for (int f = 0; f < 4; f++) oacc[dj][f] = 0.f;
    float m0 = -3e38f, m1 = -3e38f, l0 = 0.f, l1 = 0.f;

    const int NTL = TT / 128;   // 16
    for (int t = 0; t < NTL; t++) {
        int st = t & 1;
        cpwait<0>();
        __syncthreads();
        if (t + 1 < NTL) pfkv(t + 1, st ^ 1);

        float s[16][4];
        #pragma unroll
        for (int nj = 0; nj < 16; nj++)
            #pragma unroll
            for (int f = 0; f < 4; f++) s[nj][f] = 0.f;
        #pragma unroll
        for (int kt = 0; kt < 4; kt++) {
            #pragma unroll
            for (int nb = 0; nb < 8; nb++) {
                uint32_t off = (uint32_t)((st*KSTG + (nb*16 + b_row)*72
                                           + kt*16 + b_k) * 2);
                uint32_t h0,h1,h2,h3, e0,e1,e2,e3;
                LDM_X4(h0,h1,h2,h3, sKh + off);
                LDM_X4(e0,e1,e2,e3, sKl + off);
                int nj = nb * 2;
                MMA_F16(s[nj], qfh[kt][0],qfh[kt][1],qfh[kt][2],qfh[kt][3], e0,e1);
                MMA_F16(s[nj], qfl[kt][0],qfl[kt][1],qfl[kt][2],qfl[kt][3], h0,h1);
                MMA_F16(s[nj], qfh[kt][0],qfh[kt][1],qfh[kt][2],qfh[kt][3], h0,h1);
                MMA_F16(s[nj+1], qfh[kt][0],qfh[kt][1],qfh[kt][2],qfh[kt][3], e2,e3);
                MMA_F16(s[nj+1], qfl[kt][0],qfl[kt][1],qfl[kt][2],qfl[kt][3], h2,h3);
                MMA_F16(s[nj+1], qfh[kt][0],qfh[kt][1],qfh[kt][2],qfh[kt][3], h2,h3);
            }
        }
        // ---- online softmax (log2 domain: p = 2^(s-m)) ----
        float mt0 = -3e38f, mt1 = -3e38f;
        #pragma unroll
        for (int nj = 0; nj < 16; nj++) {
            mt0 = fmaxf(mt0, fmaxf(s[nj][0], s[nj][1]));
            mt1 = fmaxf(mt1, fmaxf(s[nj][2], s[nj][3]));
        }
        mt0 = fmaxf(mt0, __shfl_xor_sync(0xffffffffu, mt0, 1));
        mt0 = fmaxf(mt0, __shfl_xor_sync(0xffffffffu, mt0, 2));
        mt1 = fmaxf(mt1, __shfl_xor_sync(0xffffffffu, mt1, 1));
        mt1 = fmaxf(mt1, __shfl_xor_sync(0xffffffffu, mt1, 2));
        float mn0 = fmaxf(m0, mt0), mn1 = fmaxf(m1, mt1);
        float al0 = ex2f(m0 - mn0), al1 = ex2f(m1 - mn1);
        float ps0 = 0.f, ps1 = 0.f;
        int pr0 = (16*warp + lr) * PP, pr1 = (16*warp + 8 + lr) * PP;
        #pragma unroll
        for (int nj = 0; nj < 16; nj++) {
            float p0 = ex2f(s[nj][0] - mn0);
            float p1 = ex2f(s[nj][1] - mn0);
            float p2 = ex2f(s[nj][2] - mn1);
            float p3 = ex2f(s[nj][3] - mn1);
            ps0 += p0 + p1; ps1 += p2 + p3;
            *(half2*)(Ph + pr0 + nj*8 + 2*lc) = __floats2half2_rn(p0, p1);
            *(half2*)(Ph + pr1 + nj*8 + 2*lc) = __floats2half2_rn(p2, p3);
        }
        ps0 += __shfl_xor_sync(0xffffffffu, ps0, 1);
        ps0 += __shfl_xor_sync(0xffffffffu, ps0, 2);
        ps1 += __shfl_xor_sync(0xffffffffu, ps1, 1);
        ps1 += __shfl_xor_sync(0xffffffffu, ps1, 2);
        l0 = l0 * al0 + ps0;
        l1 = l1 * al1 + ps1;
        m0 = mn0; m1 = mn1;
        #pragma unroll
        for (int dj = 0; dj < 8; dj++) {
            oacc[dj][0] *= al0; oacc[dj][1] *= al0;
            oacc[dj][2] *= al1; oacc[dj][3] *= al1;
        }
        __syncwarp();
        #pragma unroll
        for (int kt = 0; kt < 8; kt++) {
            uint32_t pa0,pa1,pa2,pa3;
            LDM_X4(pa0,pa1,pa2,pa3,
                   sPh + (uint32_t)(((16*warp + a_row)*PP + kt*16 + a_k) * 2));
            #pragma unroll
            for (int dp = 0; dp < 4; dp++) {
                uint32_t v0,v1,v2,v3;
                uint32_t ad = sVs + (uint32_t)((st*KSTG + (kt*16 + v_row)*72
                                                + dp*16 + v_d) * 2);
                LDM_X4T(v0,v1,v2,v3, ad);
                MMA_F16(oacc[dp*2],   pa0,pa1,pa2,pa3, v0,v1);
                MMA_F16(oacc[dp*2+1], pa0,pa1,pa2,pa3, v2,v3);
            }
        }
    }
    float inv0 = 1.f / l0, inv1 = 1.f / l1;
    int row0 = r0 + 16*warp + lr, row1 = row0 + 8;
    #pragma unroll
    for (int dj = 0; dj < 8; dj++) {
        int col = dj*8 + 2*lc;
        *(half2*)(O_ + base + (size_t)row0 * CC + col) =
            __floats2half2_rn(oacc[dj][0]*inv0, oacc[dj][1]*inv0);
        *(half2*)(O_ + base + (size_t)row1 * CC + col) =
            __floats2half2_rn(oacc[dj][2]*inv1, oacc[dj][3]*inv1);
    }
}

// ========================= launch =========================
extern "C" void kernel_launch(void* const* d_in, const int* in_sizes, int n_in,
                              void* d_out, int out_size) {
    const float* x     = (const float*)d_in[0];
    const float* Wq    = (const float*)d_in[1];
    const float* bq    = (const float*)d_in[2];
    const float* Wk    = (const float*)d_in[3];
    const float* bk    = (const float*)d_in[4];
    const float* Wv    = (const float*)d_in[5];
    const float* bv    = (const float*)d_in[6];
    const float* Wo    = (const float*)d_in[7];
    const float* bo    = (const float*)d_in[8];
    const float* ln1g  = (const float*)d_in[9];
    const float* ln1b  = (const float*)d_in[10];
    const float* ln2g  = (const float*)d_in[11];
    const float* ln2b  = (const float*)d_in[12];
    const float* W1    = (const float*)d_in[13];
    const float* b1    = (const float*)d_in[14];
    const float* W2    = (const float*)d_in[15];
    const float* b2    = (const float*)d_in[16];
    float* out = (float*)d_out;

    __half *xnh,*xnl,*qh,*ql,*kh,*kl,*vh,*oh,*x2h,*ffh,*wqh,*wql,*wot,*w1t,*w2t;
    float *x1;
    cudaGetSymbolAddress((void**)&xnh, g_xnh);
    cudaGetSymbolAddress((void**)&xnl, g_xnl);
    cudaGetSymbolAddress((void**)&qh,  g_qhh);
    cudaGetSymbolAddress((void**)&ql,  g_qll);
    cudaGetSymbolAddress((void**)&kh,  g_khh);
    cudaGetSymbolAddress((void**)&kl,  g_kll);
    cudaGetSymbolAddress((void**)&vh,  g_vhh);
    cudaGetSymbolAddress((void**)&oh,  g_ohh);
    cudaGetSymbolAddress((void**)&x2h, g_x2h);
    cudaGetSymbolAddress((void**)&ffh, g_ffh);
    cudaGetSymbolAddress((void**)&x1,  g_x1);
    cudaGetSymbolAddress((void**)&wqh, g_wqh);
    cudaGetSymbolAddress((void**)&wql, g_wql);
    cudaGetSymbolAddress((void**)&wot, g_wot);
    cudaGetSymbolAddress((void**)&w1t, g_w1t);
    cudaGetSymbolAddress((void**)&w2t, g_w2t);

    cudaFuncSetAttribute(gemm_qkv_h, cudaFuncAttributeMaxDynamicSharedMemorySize, QKV_SMEM);
    cudaFuncSetAttribute(attn_h, cudaFuncAttributeMaxDynamicSharedMemorySize, ATSMH);
    cudaFuncSetAttribute(gemm_h<false,true,false>,
                         cudaFuncAttributeMaxDynamicSharedMemorySize, G_SMEM);
    cudaFuncSetAttribute(gemm_h<true,false,true>,
                         cudaFuncAttributeMaxDynamicSharedMemorySize, G_SMEM);

    // weight prep
    prep_qkv_h<<<dim3(16, 48), 256>>>(Wq, Wk, Wv, wqh, wql);
    prep_t<<<dim3(16, 16), 256>>>(Wo, wot, 1024, 1024);
    prep_t<<<dim3(64, 16), 256>>>(W1, w1t, 1024, 4096);
    prep_t<<<dim3(16, 64), 256>>>(W2, w2t, 4096, 1024);

    // 1) LN1 (hi+lo fp16), warp-per-row
    ln_h<2><<<MM/8, 256>>>(x, ln1g, ln1b, xnh, xnl);
    // 2) QKV (3-term fp16 for Q/K, 1-term for V, S=2)
    gemm_qkv_h<<<dim3(24, 64), 256, QKV_SMEM>>>(xnh, xnl, wqh, wql,
                                                bq, bk, bv, qh, ql, kh, kl, vh);
    // 3) attention (fp16 TC flash, BC=128, log2 softmax)
    attn_h<<<dim3(TT/128, HH, BB), 256, ATSMH>>>(qh, ql, kh, kl, vh, oh);
    // 4) out proj + residual -> x1 (fp32)
    gemm_h<false, true, false><<<dim3(8, 64), 256, G_SMEM>>>(oh, wot, bo, x, (void*)x1, MM, CC, CC);
    // 5) LN2 (fp16 hi), warp-per-row
    ln_h<1><<<MM/8, 256>>>(x1, ln2g, ln2b, x2h, nullptr);
    // 6) FFN1 (relu, fp16 out)
    gemm_h<true, false, true><<<dim3(32, 64), 256, G_SMEM>>>(x2h, w1t, b1, nullptr, (void*)ffh, MM, DFF, CC);
    // 7) FFN2 + residual -> out (fp32)
    gemm_h<false, true, false><<<dim3(8, 64), 256, G_SMEM>>>(ffh, w2t, b2, x1, (void*)out, MM, CC, DFF);
}

// round 15
// speedup vs baseline: 1.1047x; 1.0071x over previous
#include <cuda_runtime.h>
#include <cuda_fp16.h>
#include <math.h>
#include <stdint.h>

#define BB 4
#define TT 2048
#define CC 1024
#define HH 16
#define DHH 64
#define DFF 4096
#define MM (BB*TT)   /* 8192 */

// -------- scratch (device globals; no allocation) --------
__device__ __half g_xnh[(size_t)MM*CC];
__device__ __half g_xnl[(size_t)MM*CC];
__device__ __half g_qhh[(size_t)MM*CC];
__device__ __half g_qll[(size_t)MM*CC];
__device__ __half g_khh[(size_t)MM*CC];
__device__ __half g_kll[(size_t)MM*CC];
__device__ __half g_vhh[(size_t)MM*CC];
__device__ __half g_ohh[(size_t)MM*CC];
__device__ __half g_x2h[(size_t)MM*CC];
__device__ __half g_ffh[(size_t)MM*DFF];
__device__ float  g_x1 [(size_t)MM*CC];
__device__ __half g_wqh[(size_t)CC*3072];
__device__ __half g_wql[(size_t)CC*3072];
__device__ __half g_wot[(size_t)CC*CC];
__device__ __half g_w1t[(size_t)CC*DFF];
__device__ __half g_w2t[(size_t)DFF*CC];

// ======================= helpers =======================
__device__ __forceinline__ uint32_t smem_u32(const void* p) {
    return (uint32_t)__cvta_generic_to_shared(p);
}
__device__ __forceinline__ float ex2f(float x) {
    float r;
    asm("ex2.approx.f32 %0, %1;" : "=f"(r) : "f"(x));
    return r;
}
__device__ __forceinline__ half2 h2ex2(float a, float b) {
    half2 h = __floats2half2_rn(a, b);
    uint32_t u = *(uint32_t*)&h, r;
    asm("ex2.approx.f16x2 %0, %1;" : "=r"(r) : "r"(u));
    return *(half2*)&r;
}
#define LDM_X4(r0,r1,r2,r3, addr) \
    asm volatile("ldmatrix.sync.aligned.m8n8.x4.shared.b16 {%0,%1,%2,%3},[%4];" \
        : "=r"(r0),"=r"(r1),"=r"(r2),"=r"(r3) : "r"(addr))
#define LDM_X4T(r0,r1,r2,r3, addr) \
    asm volatile("ldmatrix.sync.aligned.m8n8.x4.trans.shared.b16 {%0,%1,%2,%3},[%4];" \
        : "=r"(r0),"=r"(r1),"=r"(r2),"=r"(r3) : "r"(addr))
#define MMA_F16(d, a0,a1,a2,a3, b0,b1) \
    asm volatile("mma.sync.aligned.m16n8k16.row.col.f32.f16.f16.f32 " \
        "{%0,%1,%2,%3},{%4,%5,%6,%7},{%8,%9},{%0,%1,%2,%3};" \
        : "+f"(d[0]),"+f"(d[1]),"+f"(d[2]),"+f"(d[3]) \
        : "r"(a0),"r"(a1),"r"(a2),"r"(a3),"r"(b0),"r"(b1))

__device__ __forceinline__ void cpa16(uint32_t dst, const void* src) {
    asm volatile("cp.async.cg.shared.global [%0], [%1], 16;\n" :: "r"(dst), "l"(src));
}
__device__ __forceinline__ void cpcommit() { asm volatile("cp.async.commit_group;\n" ::); }
template<int N> __device__ __forceinline__ void cpwait() {
    asm volatile("cp.async.wait_group %0;\n" :: "n"(N));
}

// ======================= fused prep + LN1 =======================
// blocks [0,768): Wqkv hi/lo transpose; [768,1024): Wo; [1024,2048): W1;
// [2048,3072): W2; [3072,4096): LN1 (8 rows/block, warp-per-row).
__global__ void prep_all(const float* __restrict__ Wq, const float* __restrict__ Wk,
                         const float* __restrict__ Wv, const float* __restrict__ Wo,
                         const float* __restrict__ W1, const float* __restrict__ W2,
                         const float* __restrict__ x,
                         const float* __restrict__ g1, const float* __restrict__ b1v,
                         __half* __restrict__ wqh, __half* __restrict__ wql,
                         __half* __restrict__ wot, __half* __restrict__ w1t,
                         __half* __restrict__ w2t,
                         __half* __restrict__ xnh, __half* __restrict__ xnl) {
    int bid = blockIdx.x;
    int tid = threadIdx.x;
    if (bid >= 3072) {
        // ---- LN1, warp-per-row, hi+lo fp16 ----
        int warp = tid >> 5, lane = tid & 31;
        int row = (bid - 3072) * 8 + warp;
        const float* xr = x + (size_t)row * CC;
        float4 v[8];
        float s = 0.f, ss = 0.f;
        #pragma unroll
        for (int i = 0; i < 8; i++) {
            v[i] = *(const float4*)(xr + i * 128 + lane * 4);
            s  += v[i].x + v[i].y + v[i].z + v[i].w;
            ss += v[i].x*v[i].x + v[i].y*v[i].y + v[i].z*v[i].z + v[i].w*v[i].w;
        }
        #pragma unroll
        for (int off = 16; off >= 1; off >>= 1) {
            s  += __shfl_xor_sync(0xffffffffu, s,  off);
            ss += __shfl_xor_sync(0xffffffffu, ss, off);
        }
        float mu  = s * (1.0f / CC);
        float var = ss * (1.0f / CC) - mu * mu;
        float rs  = rsqrtf(var + 1e-5f);
        #pragma unroll
        for (int i = 0; i < 8; i++) {
            int col = i * 128 + lane * 4;
            float4 gv = *(const float4*)(g1 + col);
            float4 bv = *(const float4*)(b1v + col);
            float y0 = (v[i].x - mu) * rs * gv.x + bv.x;
            float y1 = (v[i].y - mu) * rs * gv.y + bv.y;
            float y2 = (v[i].z - mu) * rs * gv.z + bv.z;
            float y3 = (v[i].w - mu) * rs * gv.w + bv.w;
            __half h0 = __float2half_rn(y0), h1 = __float2half_rn(y1);
            __half h2 = __float2half_rn(y2), h3 = __float2half_rn(y3);
            half2 a = __halves2half2(h0, h1);
            half2 b = __halves2half2(h2, h3);
            uint2 u; u.x = *(uint32_t*)&a; u.y = *(uint32_t*)&b;
            *(uint2*)(xnh + (size_t)row * CC + col) = u;
            half2 c = __halves2half2(__float2half_rn(y0 - __half2float(h0)),
                                     __float2half_rn(y1 - __half2float(h1)));
            half2 d = __halves2half2(__float2half_rn(y2 - __half2float(h2)),
                                     __float2half_rn(y3 - __half2float(h3)));
            uint2 w; w.x = *(uint32_t*)&c; w.y = *(uint32_t*)&d;
            *(uint2*)(xnl + (size_t)row * CC + col) = w;
        }
        return;
    }
    // ---- weight transpose 64x64 tile ----
    __shared__ float t[64][65];
    const float* Wsrc; __half* Th; __half* Tl = nullptr;
    int rs, cb, outN0, outK, k0;
    if (bid < 768) {
        int kt = bid & 15, nt = bid >> 4;
        int mat = nt >> 4, h = nt & 15;
        const float* W = (mat == 0) ? Wq : (mat == 1) ? Wk : Wv;
        Wsrc = W + h * 65536; rs = 64; cb = 0;
        k0 = kt * 64;
        outN0 = mat * 1024 + h * 64; outK = 1024;
        Th = wqh; Tl = wql;
    } else if (bid < 1024) {
        int idx = bid - 768;
        int n0 = (idx & 15) * 64; k0 = (idx >> 4) * 64;
        Wsrc = Wo; rs = 1024; cb = n0;
        outN0 = n0; outK = 1024; Th = wot;
    } else if (bid < 2048) {
        int idx = bid - 1024;
        int n0 = (idx & 63) * 64; k0 = (idx >> 6) * 64;
        Wsrc = W1; rs = 4096; cb = n0;
        outN0 = n0; outK = 1024; Th = w1t;
    } else {
        int idx = bid - 2048;
        int n0 = (idx & 15) * 64; k0 = (idx >> 4) * 64;
        Wsrc = W2; rs = 1024; cb = n0;
        outN0 = n0; outK = 4096; Th = w2t;
    }
    int ty = tid >> 4, tx = tid & 15;
    #pragma unroll
    for (int j = 0; j < 4; j++) {
        int ky = ty + 16 * j;
        float4 v = *(const float4*)(Wsrc + (size_t)(k0 + ky) * rs + cb + tx * 4);
        t[ky][tx*4+0] = v.x; t[ky][tx*4+1] = v.y;
        t[ky][tx*4+2] = v.z; t[ky][tx*4+3] = v.w;
    }
    __syncthreads();
    int nr = tid >> 2, kc = (tid & 3) * 16;
    __half hh[16], hl[16];
    bool split = (Tl != nullptr);
    #pragma unroll
    for (int i = 0; i < 16; i++) {
        float w = t[kc + i][nr];
        __half hi = __float2half_rn(w);
        hh[i] = hi;
        if (split) hl[i] = __float2half_rn(w - __half2float(hi));
    }
    uint4* dh = (uint4*)(Th + (size_t)(outN0 + nr) * outK + k0 + kc);
    dh[0] = *(uint4*)&hh[0]; dh[1] = *(uint4*)&hh[8];
    if (split) {
        uint4* dl = (uint4*)(Tl + (size_t)(outN0 + nr) * outK + k0 + kc);
        dl[0] = *(uint4*)&hl[0]; dl[1] = *(uint4*)&hl[8];
    }
}

// ======================= LayerNorm (LN2): warp-per-row =======================
__global__ void ln_h1(const float* __restrict__ X, const float* __restrict__ gam,
                      const float* __restrict__ bet, __half* __restrict__ Yh) {
    int warp = threadIdx.x >> 5, lane = threadIdx.x & 31;
    int row = blockIdx.x * 8 + warp;
    const float* xr = X + (size_t)row * CC;
    float4 v[8];
    float s = 0.f, ss = 0.f;
    #pragma unroll
    for (int i = 0; i < 8; i++) {
        v[i] = *(const float4*)(xr + i * 128 + lane * 4);
        s  += v[i].x + v[i].y + v[i].z + v[i].w;
        ss += v[i].x*v[i].x + v[i].y*v[i].y + v[i].z*v[i].z + v[i].w*v[i].w;
    }
    #pragma unroll
    for (int off = 16; off >= 1; off >>= 1) {
        s  += __shfl_xor_sync(0xffffffffu, s,  off);
        ss += __shfl_xor_sync(0xffffffffu, ss, off);
    }
    float mu  = s * (1.0f / CC);
    float var = ss * (1.0f / CC) - mu * mu;
    float rs  = rsqrtf(var + 1e-5f);
    #pragma unroll
    for (int i = 0; i < 8; i++) {
        int col = i * 128 + lane * 4;
        float4 gv = *(const float4*)(gam + col);
        float4 bv = *(const float4*)(bet + col);
        float y0 = (v[i].x - mu) * rs * gv.x + bv.x;
        float y1 = (v[i].y - mu) * rs * gv.y + bv.y;
        float y2 = (v[i].z - mu) * rs * gv.z + bv.z;
        float y3 = (v[i].w - mu) * rs * gv.w + bv.w;
        half2 a = __floats2half2_rn(y0, y1);
        half2 b = __floats2half2_rn(y2, y3);
        uint2 u; u.x = *(uint32_t*)&a; u.y = *(uint32_t*)&b;
        *(uint2*)(Yh + (size_t)row * CC + col) = u;
    }
}

// ============ fp16 GEMM: 128x128x32 tiles, 4-stage pipeline, occ 2 ============
#define GP 40                 // smem pitch in halves
#define GST 5120              // stage stride in halves (128*40)
#define NSTG 4
#define G_SMEM (NSTG*GST*2*2) // 81920 bytes
template<bool RELU, bool RESID, bool OUTH>
__global__ __launch_bounds__(256, 2) void gemm_h(
        const __half* __restrict__ A, const __half* __restrict__ Bt,
        const float* __restrict__ bias, const float* __restrict__ resid,
        void* __restrict__ Cv, int M, int N, int K) {
    extern __shared__ __half gsm[];
    __half* As = gsm;                 // [NSTG][GST]
    __half* Bs = gsm + NSTG*GST;
    int tid = threadIdx.x, l = tid & 31, warp = tid >> 5;
    int wy = warp >> 2, wx = warp & 3, lr = l >> 2, lc = l & 3;
    int m0 = blockIdx.y * 128, n0 = blockIdx.x * 128;
    int a_row = (l & 7) + ((l >> 3) & 1) * 8, a_k = (l >> 4) * 8;
    int b_row = (l & 7) + ((l >> 4) & 1) * 8, b_k = ((l >> 3) & 1) * 8;
    float acc[4][4][4];
    #pragma unroll
    for (int i = 0; i < 4; i++)
        #pragma unroll
        for (int j = 0; j < 4; j++)
            #pragma unroll
            for (int f = 0; f < 4; f++) acc[i][j][f] = 0.f;
    uint32_t sA = smem_u32(As), sB = smem_u32(Bs);
    int r1c = tid >> 2, g1c = tid & 3;
    int r2c = (tid + 256) >> 2;
    const int NT = K >> 5;
    auto loadT = [&](int kt, int st) {
        int k0 = kt * 32;
        uint32_t o1 = (uint32_t)((st*GST + r1c*GP + g1c*8) * 2);
        uint32_t o2 = (uint32_t)((st*GST + r2c*GP + g1c*8) * 2);
        cpa16(sA + o1, A + (size_t)(m0 + r1c) * K + k0 + g1c*8);
        cpa16(sA + o2, A + (size_t)(m0 + r2c) * K + k0 + g1c*8);
        cpa16(sB + o1, Bt + (size_t)(n0 + r1c) * K + k0 + g1c*8);
        cpa16(sB + o2, Bt + (size_t)(n0 + r2c) * K + k0 + g1c*8);
        cpcommit();
    };
    loadT(0, 0);
    loadT(1, 1);
    loadT(2, 2);
    int st = 0, ldst = 3;
    for (int kt = 0; kt < NT; kt++) {
        cpwait<NSTG-2>();
        __syncthreads();
        if (kt + 3 < NT) {
            loadT(kt + 3, ldst);
            if (++ldst == NSTG) ldst = 0;
        }
        #pragma unroll
        for (int ks = 0; ks < 2; ks++) {
            uint32_t af[4][4], bf[4][2];
            #pragma unroll
            for (int mi = 0; mi < 4; mi++) {
                uint32_t ad = sA + (uint32_t)((st*GST + (wy*64 + mi*16 + a_row)*GP
                                               + ks*16 + a_k) * 2);
                LDM_X4(af[mi][0], af[mi][1], af[mi][2], af[mi][3], ad);
            }
            #pragma unroll
            for (int nb = 0; nb < 2; nb++) {
                uint32_t ad = sB + (uint32_t)((st*GST + (wx*32 + nb*16 + b_row)*GP
                                               + ks*16 + b_k) * 2);
                uint32_t q0,q1,q2,q3;
                LDM_X4(q0,q1,q2,q3, ad);
                bf[nb*2][0]=q0; bf[nb*2][1]=q1; bf[nb*2+1][0]=q2; bf[nb*2+1][1]=q3;
            }
            #pragma unroll
            for (int mi = 0; mi < 4; mi++)
                #pragma unroll
                for (int nj = 0; nj < 4; nj++)
                    MMA_F16(acc[mi][nj], af[mi][0],af[mi][1],af[mi][2],af[mi][3],
                            bf[nj][0], bf[nj][1]);
        }
        if (++st == NSTG) st = 0;
    }
    #pragma unroll
    for (int mi = 0; mi < 4; mi++) {
        #pragma unroll
        for (int nj = 0; nj < 4; nj++) {
            int row = m0 + wy*64 + mi*16 + lr;
            int col = n0 + wx*32 + nj*8 + 2*lc;
            float b0 = bias[col], b1 = bias[col+1];
            float v0 = acc[mi][nj][0] + b0, v1 = acc[mi][nj][1] + b1;
            float v2 = acc[mi][nj][2] + b0, v3 = acc[mi][nj][3] + b1;
            if (RESID) {
                float2 q0 = *(const float2*)(resid + (size_t)row * N + col);
                float2 q1 = *(const float2*)(resid + (size_t)(row+8) * N + col);
                v0 += q0.x; v1 += q0.y; v2 += q1.x; v3 += q1.y;
            }
            if (RELU) {
                v0 = fmaxf(v0, 0.f); v1 = fmaxf(v1, 0.f);
                v2 = fmaxf(v2, 0.f); v3 = fmaxf(v3, 0.f);
            }
            if (OUTH) {
                __half* C = (__half*)Cv;
                *(half2*)(C + (size_t)row * N + col)     = __floats2half2_rn(v0, v1);
                *(half2*)(C + (size_t)(row+8) * N + col) = __floats2half2_rn(v2, v3);
            } else {
                float* C = (float*)Cv;
                *(float2*)(C + (size_t)row * N + col)     = make_float2(v0, v1);
                *(float2*)(C + (size_t)(row+8) * N + col) = make_float2(v2, v3);
            }
        }
    }
}

// ============ QKV GEMM: 3-term fp16 for Q/K tiles, 1-term for V tiles ============
#define QST 5120
#define QKV_SMEM (2*QST*4*2)   // 81920 B
__global__ __launch_bounds__(256) void gemm_qkv_h(
        const __half* __restrict__ Ah_, const __half* __restrict__ Al_,
        const __half* __restrict__ Bh_, const __half* __restrict__ Bl_,
        const float* __restrict__ bq, const float* __restrict__ bk_,
        const float* __restrict__ bv_,
        __half* __restrict__ qh, __half* __restrict__ ql,
        __half* __restrict__ kh, __half* __restrict__ kl,
        __half* __restrict__ vh) {
    extern __shared__ __half smq[];
    __half* Ah = smq;            // [2][5120]
    __half* Al = smq + 10240;
    __half* Bh = smq + 20480;
    __half* Bl = smq + 30720;
    const int K = CC;
    int tid = threadIdx.x, l = tid & 31, warp = tid >> 5;
    int wy = warp >> 2, wx = warp & 3, lr = l >> 2, lc = l & 3;
    int m0 = blockIdx.y * 128, n0 = blockIdx.x * 128;
    int mat = n0 >> 10;
    const bool three = (mat < 2);
    int a_row = (l & 7) + ((l >> 3) & 1) * 8, a_k = (l >> 4) * 8;
    int b_row = (l & 7) + ((l >> 4) & 1) * 8, b_k = ((l >> 3) & 1) * 8;
    float acc[4][4][4];
    #pragma unroll
    for (int i = 0; i < 4; i++)
        #pragma unroll
        for (int j = 0; j < 4; j++)
            #pragma unroll
            for (int f = 0; f < 4; f++) acc[i][j][f] = 0.f;
    uint32_t sAh = smem_u32(Ah), sAl = smem_u32(Al);
    uint32_t sBh = smem_u32(Bh), sBl = smem_u32(Bl);
    int r1c = tid >> 2, g1c = tid & 3;
    int r2c = (tid + 256) >> 2;
    const int NT = K >> 5;
    auto pf = [&](int kt, int st) {
        int k0 = kt * 32;
        uint32_t o1 = (uint32_t)((st*QST + r1c*GP + g1c*8) * 2);
        uint32_t o2 = (uint32_t)((st*QST + r2c*GP + g1c*8) * 2);
        cpa16(sAh + o1, Ah_ + (size_t)(m0 + r1c) * K + k0 + g1c*8);
        cpa16(sAh + o2, Ah_ + (size_t)(m0 + r2c) * K + k0 + g1c*8);
        cpa16(sBh + o1, Bh_ + (size_t)(n0 + r1c) * K + k0 + g1c*8);
        cpa16(sBh + o2, Bh_ + (size_t)(n0 + r2c) * K + k0 + g1c*8);
        if (three) {
            cpa16(sAl + o1, Al_ + (size_t)(m0 + r1c) * K + k0 + g1c*8);
            cpa16(sAl + o2, Al_ + (size_t)(m0 + r2c) * K + k0 + g1c*8);
            cpa16(sBl + o1, Bl_ + (size_t)(n0 + r1c) * K + k0 + g1c*8);
            cpa16(sBl + o2, Bl_ + (size_t)(n0 + r2c) * K + k0 + g1c*8);
        }
        cpcommit();
    };
    pf(0, 0);
    for (int kt = 0; kt < NT; kt++) {
        int st = kt & 1;
        cpwait<0>();
        __syncthreads();
        if (kt + 1 < NT) pf(kt + 1, st ^ 1);
        #pragma unroll
        for (int ks = 0; ks < 2; ks++) {
            uint32_t afh[4][4], afl[4][4];
            #pragma unroll
            for (int mi = 0; mi < 4; mi++) {
                uint32_t ao = (uint32_t)((st*QST + (wy*64 + mi*16 + a_row)*GP
                                          + ks*16 + a_k) * 2);
                LDM_X4(afh[mi][0], afh[mi][1], afh[mi][2], afh[mi][3], sAh + ao);
                if (three)
                    LDM_X4(afl[mi][0], afl[mi][1], afl[mi][2], afl[mi][3], sAl + ao);
            }
            #pragma unroll
            for (int nb = 0; nb < 2; nb++) {
                uint32_t bo = (uint32_t)((st*QST + (wx*32 + nb*16 + b_row)*GP
                                          + ks*16 + b_k) * 2);
                uint32_t h0,h1,h2,h3, e0,e1,e2,e3;
                LDM_X4(h0,h1,h2,h3, sBh + bo);
                if (three) { LDM_X4(e0,e1,e2,e3, sBl + bo); }
                #pragma unroll
                for (int mi = 0; mi < 4; mi++) {
                    int nj = nb * 2;
                    if (three) {
                        MMA_F16(acc[mi][nj], afh[mi][0],afh[mi][1],afh[mi][2],afh[mi][3], e0,e1);
                        MMA_F16(acc[mi][nj], afl[mi][0],afl[mi][1],afl[mi][2],afl[mi][3], h0,h1);
                        MMA_F16(acc[mi][nj+1], afh[mi][0],afh[mi][1],afh[mi][2],afh[mi][3], e2,e3);
                        MMA_F16(acc[mi][nj+1], afl[mi][0],afl[mi][1],afl[mi][2],afl[mi][3], h2,h3);
                    }
                    MMA_F16(acc[mi][nj], afh[mi][0],afh[mi][1],afh[mi][2],afh[mi][3], h0,h1);
                    MMA_F16(acc[mi][nj+1], afh[mi][0],afh[mi][1],afh[mi][2],afh[mi][3], h2,h3);
                }
            }
        }
    }
    int rem0 = n0 & 1023;
    const float* bias = (mat == 0) ? bq : (mat == 1) ? bk_ : bv_;
    // Q scaled by 8*log2(e): softmax runs in log2 domain
    float sc = (mat == 0) ? 8.0f * 1.4426950408889634f : 1.f;
    #pragma unroll
    for (int mi = 0; mi < 4; mi++) {
        #pragma unroll
        for (int nj = 0; nj < 4; nj++) {
            int row = m0 + wy*64 + mi*16 + lr;
            int col = rem0 + wx*32 + nj*8 + 2*lc;
            float b0 = bias[col], b1 = bias[col+1];
            float v0 = (acc[mi][nj][0] + b0) * sc, v1 = (acc[mi][nj][1] + b1) * sc;
            float v2 = (acc[mi][nj][2] + b0) * sc, v3 = (acc[mi][nj][3] + b1) * sc;
            size_t i0 = (size_t)row * CC + col, i1 = (size_t)(row+8) * CC + col;
            if (mat == 2) {
                *(half2*)(vh + i0) = __floats2half2_rn(v0, v1);
                *(half2*)(vh + i1) = __floats2half2_rn(v2, v3);
            } else {
                __half* oh = (mat == 0) ? qh : kh;
                __half* ol = (mat == 0) ? ql : kl;
                __half h0 = __float2half_rn(v0), h1 = __float2half_rn(v1);
                __half h2 = __float2half_rn(v2), h3 = __float2half_rn(v3);
                *(half2*)(oh + i0) = __halves2half2(h0, h1);
                *(half2*)(oh + i1) = __halves2half2(h2, h3);
                *(half2*)(ol + i0) = __halves2half2(
                    __float2half_rn(v0 - __half2float(h0)),
                    __float2half_rn(v1 - __half2float(h1)));
                *(half2*)(ol + i1) = __halves2half2(
                    __float2half_rn(v2 - __half2float(h2)),
                    __float2half_rn(v3 - __half2float(h3)));
            }
        }
    }
}

// ================= fp16 flash attention, BC=128, f16x2 log2 softmax =================
#define PP 136
#define KSTG 9216
#define ATSMH (72704*2)
__global__ __launch_bounds__(256, 1) void attn_h(
        const __half* __restrict__ Qh_, const __half* __restrict__ Ql_,
        const __half* __restrict__ Kh_, const __half* __restrict__ Kl_,
        const __half* __restrict__ V_, __half* __restrict__ O_) {
    extern __shared__ __half sma[];
    __half* Ph = sma;
    __half* Kh = sma + 17408;
    __half* Kl = sma + 35840;
    __half* Vs = sma + 54272;
    uint32_t sPh = smem_u32(Ph), sKh = smem_u32(Kh), sKl = smem_u32(Kl), sVs = smem_u32(Vs);
    int tid = threadIdx.x, lane = tid & 31, warp = tid >> 5;
    int lr = lane >> 2, lc = lane & 3;
    int r0 = blockIdx.x * 128;
    int h  = blockIdx.y;
    int b  = blockIdx.z;
    size_t base = (size_t)b * TT * CC + h * DHH;

    int a_row = (lane & 7) + ((lane >> 3) & 1) * 8, a_k = (lane >> 4) * 8;
    int b_row = (lane & 7) + ((lane >> 4) & 1) * 8, b_k = ((lane >> 3) & 1) * 8;
    int v_row = (lane & 7) + ((lane >> 3) & 1) * 8, v_d = (lane >> 4) * 8;

    int c1r = tid >> 3, c1g = tid & 7;
    auto pfkv = [&](int t, int st) {
        int s0 = t * 128;
        #pragma unroll
        for (int i = 0; i < 4; i++) {
            int r = c1r + 32 * i;
            uint32_t o = (uint32_t)((st*KSTG + r*72 + c1g*8) * 2);
            size_t g = base + (size_t)(s0 + r) * CC + c1g*8;
            cpa16(sKh + o, Kh_ + g);
            cpa16(sKl + o, Kl_ + g);
            cpa16(sVs + o, V_ + g);
        }
        cpcommit();
    };
    pfkv(0, 0);

    uint32_t qfh[4][4], qfl[4][4];
    #pragma unroll
    for (int pass = 0; pass < 2; pass++) {
        const __half* src = pass ? Ql_ : Qh_;
        #pragma unroll
        for (int i = 0; i < 4; i++) {
            int c = tid + 256 * i;
            int row = c >> 3, cg = c & 7;
            *(uint4*)(Ph + row*PP + cg*8) =
                *(const uint4*)(src + base + (size_t)(r0 + row) * CC + cg*8);
        }
        __syncthreads();
        #pragma unroll
        for (int kt = 0; kt < 4; kt++) {
            uint32_t ad = sPh + (uint32_t)(((16*warp + a_row)*PP + kt*16 + a_k) * 2);
            if (pass) { LDM_X4(qfl[kt][0], qfl[kt][1], qfl[kt][2], qfl[kt][3], ad); }
            else      { LDM_X4(qfh[kt][0], qfh[kt][1], qfh[kt][2], qfh[kt][3], ad); }
        }
        __syncthreads();
    }

    float oacc[8][4];
    #pragma unroll
    for (int dj = 0; dj < 8; dj++)
        #pragma unroll
        for (int f = 0; f < 4; f++) oacc[dj][f] = 0.f;
    float m0 = -3e38f, m1 = -3e38f, l0 = 0.f, l1 = 0.f;

    const int NTL = TT / 128;   // 16
    for (int t = 0; t < NTL; t++) {
        int st = t & 1;
        cpwait<0>();
        __syncthreads();
        if (t + 1 < NTL) pfkv(t + 1, st ^ 1);

        float s[16][4];
        #pragma unroll
        for (int nj = 0; nj < 16; nj++)
            #pragma unroll
            for (int f = 0; f < 4; f++) s[nj][f] = 0.f;
        #pragma unroll
        for (int kt = 0; kt < 4; kt++) {
            #pragma unroll
            for (int nb = 0; nb < 8; nb++) {
                uint32_t off = (uint32_t)((st*KSTG + (nb*16 + b_row)*72
                                           + kt*16 + b_k) * 2);
                uint32_t h0,h1,h2,h3, e0,e1,e2,e3;
                LDM_X4(h0,h1,h2,h3, sKh + off);
                LDM_X4(e0,e1,e2,e3, sKl + off);
                int nj = nb * 2;
                MMA_F16(s[nj], qfh[kt][0],qfh[kt][1],qfh[kt][2],qfh[kt][3], e0,e1);
                MMA_F16(s[nj], qfl[kt][0],qfl[kt][1],qfl[kt][2],qfl[kt][3], h0,h1);
                MMA_F16(s[nj], qfh[kt][0],qfh[kt][1],qfh[kt][2],qfh[kt][3], h0,h1);
                MMA_F16(s[nj+1], qfh[kt][0],qfh[kt][1],qfh[kt][2],qfh[kt][3], e2,e3);
                MMA_F16(s[nj+1], qfl[kt][0],qfl[kt][1],qfl[kt][2],qfl[kt][3], h2,h3);
                MMA_F16(s[nj+1], qfh[kt][0],qfh[kt][1],qfh[kt][2],qfh[kt][3], h2,h3);
            }
        }
        // ---- online softmax (log2 domain, fp16x2 exp) ----
        float mt0 = -3e38f, mt1 = -3e38f;
        #pragma unroll
        for (int nj = 0; nj < 16; nj++) {
            mt0 = fmaxf(mt0, fmaxf(s[nj][0], s[nj][1]));
            mt1 = fmaxf(mt1, fmaxf(s[nj][2], s[nj][3]));
        }
        mt0 = fmaxf(mt0, __shfl_xor_sync(0xffffffffu, mt0, 1));
        mt0 = fmaxf(mt0, __shfl_xor_sync(0xffffffffu, mt0, 2));
        mt1 = fmaxf(mt1, __shfl_xor_sync(0xffffffffu, mt1, 1));
        mt1 = fmaxf(mt1, __shfl_xor_sync(0xffffffffu, mt1, 2));
        float mn0 = fmaxf(m0, mt0), mn1 = fmaxf(m1, mt1);
        float al0 = ex2f(m0 - mn0), al1 = ex2f(m1 - mn1);
        float ps0 = 0.f, ps1 = 0.f;
        int pr0 = (16*warp + lr) * PP, pr1 = (16*warp + 8 + lr) * PP;
        #pragma unroll
        for (int nj = 0; nj < 16; nj++) {
            half2 p01 = h2ex2(s[nj][0] - mn0, s[nj][1] - mn0);
            half2 p23 = h2ex2(s[nj][2] - mn1, s[nj][3] - mn1);
            *(half2*)(Ph + pr0 + nj*8 + 2*lc) = p01;
            *(half2*)(Ph + pr1 + nj*8 + 2*lc) = p23;
            float2 f01 = __half22float2(p01);
            float2 f23 = __half22float2(p23);
            ps0 += f01.x + f01.y;
            ps1 += f23.x + f23.y;
        }
        ps0 += __shfl_xor_sync(0xffffffffu, ps0, 1);
        ps0 += __shfl_xor_sync(0xffffffffu, ps0, 2);
        ps1 += __shfl_xor_sync(0xffffffffu, ps1, 1);
        ps1 += __shfl_xor_sync(0xffffffffu, ps1, 2);
        l0 = l0 * al0 + ps0;
        l1 = l1 * al1 + ps1;
        m0 = mn0; m1 = mn1;
        #pragma unroll
        for (int dj = 0; dj < 8; dj++) {
            oacc[dj][0] *= al0; oacc[dj][1] *= al0;
            oacc[dj][2] *= al1; oacc[dj][3] *= al1;
        }
        __syncwarp();
        #pragma unroll
        for (int kt = 0; kt < 8; kt++) {
            uint32_t pa0,pa1,pa2,pa3;
            LDM_X4(pa0,pa1,pa2,pa3,
                   sPh + (uint32_t)(((16*warp + a_row)*PP + kt*16 + a_k) * 2));
            #pragma unroll
            for (int dp = 0; dp < 4; dp++) {
                uint32_t v0,v1,v2,v3;
                uint32_t ad = sVs + (uint32_t)((st*KSTG + (kt*16 + v_row)*72
                                                + dp*16 + v_d) * 2);
                LDM_X4T(v0,v1,v2,v3, ad);
                MMA_F16(oacc[dp*2],   pa0,pa1,pa2,pa3, v0,v1);
                MMA_F16(oacc[dp*2+1], pa0,pa1,pa2,pa3, v2,v3);
            }
        }
    }
    float inv0 = 1.f / l0, inv1 = 1.f / l1;
    int row0 = r0 + 16*warp + lr, row1 = row0 + 8;
    #pragma unroll
    for (int dj = 0; dj < 8; dj++) {
        int col = dj*8 + 2*lc;
        *(half2*)(O_ + base + (size_t)row0 * CC + col) =
            __floats2half2_rn(oacc[dj][0]*inv0, oacc[dj][1]*inv0);
        *(half2*)(O_ + base + (size_t)row1 * CC + col) =
            __floats2half2_rn(oacc[dj][2]*inv1, oacc[dj][3]*inv1);
    }
}

// ========================= launch =========================
extern "C" void kernel_launch(void* const* d_in, const int* in_sizes, int n_in,
                              void* d_out, int out_size) {
    const float* x     = (const float*)d_in[0];
    const float* Wq    = (const float*)d_in[1];
    const float* bq    = (const float*)d_in[2];
    const float* Wk    = (const float*)d_in[3];
    const float* bk    = (const float*)d_in[4];
    const float* Wv    = (const float*)d_in[5];
    const float* bv    = (const float*)d_in[6];
    const float* Wo    = (const float*)d_in[7];
    const float* bo    = (const float*)d_in[8];
    const float* ln1g  = (const float*)d_in[9];
    const float* ln1b  = (const float*)d_in[10];
    const float* ln2g  = (const float*)d_in[11];
    const float* ln2b  = (const float*)d_in[12];
    const float* W1    = (const float*)d_in[13];
    const float* b1    = (const float*)d_in[14];
    const float* W2    = (const float*)d_in[15];
    const float* b2    = (const float*)d_in[16];
    float* out = (float*)d_out;

    __half *xnh,*xnl,*qh,*ql,*kh,*kl,*vh,*oh,*x2h,*ffh,*wqh,*wql,*wot,*w1t,*w2t;
    float *x1;
    cudaGetSymbolAddress((void**)&xnh, g_xnh);
    cudaGetSymbolAddress((void**)&xnl, g_xnl);
    cudaGetSymbolAddress((void**)&qh,  g_qhh);
    cudaGetSymbolAddress((void**)&ql,  g_qll);
    cudaGetSymbolAddress((void**)&kh,  g_khh);
    cudaGetSymbolAddress((void**)&kl,  g_kll);
    cudaGetSymbolAddress((void**)&vh,  g_vhh);
    cudaGetSymbolAddress((void**)&oh,  g_ohh);
    cudaGetSymbolAddress((void**)&x2h, g_x2h);
    cudaGetSymbolAddress((void**)&ffh, g_ffh);
    cudaGetSymbolAddress((void**)&x1,  g_x1);
    cudaGetSymbolAddress((void**)&wqh, g_wqh);
    cudaGetSymbolAddress((void**)&wql, g_wql);
    cudaGetSymbolAddress((void**)&wot, g_wot);
    cudaGetSymbolAddress((void**)&w1t, g_w1t);
    cudaGetSymbolAddress((void**)&w2t, g_w2t);

    cudaFuncSetAttribute(gemm_qkv_h, cudaFuncAttributeMaxDynamicSharedMemorySize, QKV_SMEM);
    cudaFuncSetAttribute(attn_h, cudaFuncAttributeMaxDynamicSharedMemorySize, ATSMH);
    cudaFuncSetAttribute(gemm_h<false,true,false>,
                         cudaFuncAttributeMaxDynamicSharedMemorySize, G_SMEM);
    cudaFuncSetAttribute(gemm_h<true,false,true>,
                         cudaFuncAttributeMaxDynamicSharedMemorySize, G_SMEM);

    // 1) fused weight prep + LN1 (one launch)
    prep_all<<<4096, 256>>>(Wq, Wk, Wv, Wo, W1, W2, x, ln1g, ln1b,
                            wqh, wql, wot, w1t, w2t, xnh, xnl);
    // 2) QKV (3-term fp16 for Q/K, 1-term for V, S=2)
    gemm_qkv_h<<<dim3(24, 64), 256, QKV_SMEM>>>(xnh, xnl, wqh, wql,
                                                bq, bk, bv, qh, ql, kh, kl, vh);
    // 3) attention (fp16 TC flash, BC=128, f16x2 log2 softmax)
    attn_h<<<dim3(TT/128, HH, BB), 256, ATSMH>>>(qh, ql, kh, kl, vh, oh);
    // 4) out proj + residual -> x1 (fp32)
    gemm_h<false, true, false><<<dim3(8, 64), 256, G_SMEM>>>(oh, wot, bo, x, (void*)x1, MM, CC, CC);
    // 5) LN2 (fp16 hi), warp-per-row
    ln_h1<<<MM/8, 256>>>(x1, ln2g, ln2b, x2h);
    // 6) FFN1 (relu, fp16 out)
    gemm_h<true, false, true><<<dim3(32, 64), 256, G_SMEM>>>(x2h, w1t, b1, nullptr, (void*)ffh, MM, DFF, CC);
    // 7) FFN2 + residual -> out (fp32)
    gemm_h<false, true, false><<<dim3(8, 64), 256, G_SMEM>>>(ffh, w2t, b2, x1, (void*)out, MM, CC, DFF);
}